// round 13
// baseline (speedup 1.0000x reference)
#include <cuda_runtime.h>
#include <math.h>
#include <stdint.h>

#define Hc   1024
#define Nst  64
#define Lt   4096
#define OUTc 512
#define BSz  2
#define BC   (BSz*Hc)
#define CH3  342   // per-axis posenc channels

// ---------------- helpers ----------------
__device__ __forceinline__ float tf32rna(float v) {
    uint32_t u; asm("cvt.rna.tf32.f32 %0, %1;" : "=r"(u) : "f"(v));
    return __uint_as_float(u);
}
__device__ __forceinline__ float gelu_f(float s) {
    float a2 = 1.5957691216057308f * fmaf(0.044715f * s, s * s, s);
    float e  = __expf(a2);
    float th = 1.0f - __fdividef(2.0f, e + 1.0f);
    return 0.5f * s * (1.0f + th);
}
#define MMA_TF32(acc, a0,a1,a2,a3, b0,b1) \
    asm("mma.sync.aligned.m16n8k8.row.col.f32.tf32.tf32.f32 " \
        "{%0,%1,%2,%3},{%4,%5,%6,%7},{%8,%9},{%0,%1,%2,%3};" \
        : "+f"(acc[0]), "+f"(acc[1]), "+f"(acc[2]), "+f"(acc[3]) \
        : "r"(a0), "r"(a1), "r"(a2), "r"(a3), "r"(b0), "r"(b1))

// ---------------- scratch ----------------
__device__ float  g_yT[BC*Lt];          // gelu output, (b, c, l), tf32
__device__ float4 g_Wp [128*32*32];     // W fragment-packed: [kb][mb][lane]
__device__ float4 g_QtP[Hc*2048];       // per c: [kb0..7][mb0..7][lane]
__device__ float4 g_GTP[Hc*3072];       // per c: [kb0..23][mb0..3][lane]
__device__ float g_wre[Hc*Nst],  g_wim[Hc*Nst];
__device__ float g_wTre[Hc*Nst], g_wTim[Hc*Nst];   // w^64
__device__ float g_ctre[Hc*Nst], g_ctim[Hc*Nst];
__device__ float g_emb[3*16*CH3];

// ---------------- merged prep: W fragment-pack | discretize | emb ----------------
#define NWP (128*32*32)
#define NCT (Hc*Nst)
#define NEMB (3*16*CH3)

__global__ void prep_all_kernel(const float* __restrict__ W,
                                const float* __restrict__ log_dt,
                                const float* __restrict__ Are, const float* __restrict__ Aim,
                                const float* __restrict__ Cre, const float* __restrict__ Cim) {
    int idx = blockIdx.x * blockDim.x + threadIdx.x;
    if (idx < NWP) {
        int kb = idx >> 10;
        int mb = (idx >> 5) & 31;
        int ln = idx & 31;
        int g = ln >> 2, tg = ln & 3;
        int m0 = mb*16 + g, k0 = kb*8 + tg;
        float4 v;
        v.x = tf32rna(W[(size_t)k0*OUTc + m0]);
        v.y = tf32rna(W[(size_t)k0*OUTc + m0 + 8]);
        v.z = tf32rna(W[(size_t)(k0+4)*OUTc + m0]);
        v.w = tf32rna(W[(size_t)(k0+4)*OUTc + m0 + 8]);
        g_Wp[idx] = v;
        return;
    }
    int i2 = idx - NWP;
    if (i2 < NCT) {
        int c = i2 >> 6;
        double dt  = exp((double)log_dt[c]);
        double ar  = (double)Are[i2], ai = (double)Aim[i2];
        double dar = dt*ar, dai = dt*ai;
        double er  = exp(dar);
        double wr = er*cos(dai), wi = er*sin(dai);
        g_wre[i2] = (float)wr; g_wim[i2] = (float)wi;
        double erT = exp(64.0 * dar);
        g_wTre[i2] = (float)(erT*cos(64.0*dai));
        g_wTim[i2] = (float)(erT*sin(64.0*dai));
        double nr = wr - 1.0, ni = wi;
        double inv = 1.0 / (ar*ar + ai*ai);
        double qr = (nr*ar + ni*ai) * inv;
        double qi = (ni*ar - nr*ai) * inv;
        double cr = (double)Cre[i2], ci = (double)Cim[i2];
        g_ctre[i2] = (float)(2.0*(cr*qr - ci*qi));
        g_ctim[i2] = (float)(2.0*(cr*qi + ci*qr));
        return;
    }
    int i3 = i2 - NCT;
    if (i3 < NEMB) {
        int k   = i3 % CH3;
        int pos = (i3 / CH3) % 16;
        int i   = k >> 1;
        float freq = expf(-logf(10000.0f) * (float)(2*i) / (float)CH3);
        float arg  = (float)pos * freq;
        g_emb[i3] = (k & 1) ? cosf(arg) : sinf(arg);
    }
}

// ---------------- build QtP / GTP (fragment-packed) per channel ----------------
__global__ __launch_bounds__(64) void build_kernel(const float* __restrict__ D) {
    __shared__ float smre[64][65];
    __shared__ float smim[64][65];
    __shared__ float kv[64];
    int c = blockIdx.x;
    int n = threadIdx.x;
    int nn = c*64 + n;
    float wr = g_wre[nn], wi = g_wim[nn];
    float cr = g_ctre[nn], ci = g_ctim[nn];
    float4* QtP = g_QtP + (size_t)c * 2048;
    float4* GTP = g_GTP + (size_t)c * 3072;

    // phase 1: powers w^0..w^63 per state n
    {
        float pr = 1.f, pi = 0.f;
        for (int d = 0; d < 64; ++d) {
            smre[d][n] = pr; smim[d][n] = pi;
            float t = pr*wr - pi*wi; pi = pr*wi + pi*wr; pr = t;
        }
    }
    __syncthreads();
    for (int p = n; p < 2048; p += 64) {
        int kb = p >> 8, mb = (p >> 5) & 7, ln = p & 31;
        int g = ln >> 2, tg = ln & 3;
        int m0 = mb*16 + g, k0 = kb*8 + tg;
        float4 v;
        #define QV(m,k) tf32rna(((m)&1) ? smim[63-(k)][(m)>>1] : smre[63-(k)][(m)>>1])
        v.x = QV(m0,   k0); v.y = QV(m0+8, k0);
        v.z = QV(m0, k0+4); v.w = QV(m0+8, k0+4);
        #undef QV
        QtP[p] = v;
    }
    __syncthreads();
    // phase 2: z = Ct*w^{t+1}: smre[t][n]=Re, smim[t][n]=-Im
    {
        float zr = cr*wr - ci*wi, zi = cr*wi + ci*wr;
        for (int t = 0; t < 64; ++t) {
            smre[t][n] = zr; smim[t][n] = -zi;
            float tt = zr*wr - zi*wi; zi = zr*wi + zi*wr; zr = tt;
        }
    }
    __syncthreads();
    for (int p = n; p < 2048; p += 64) {
        int kb = p >> 7, mb = (p >> 5) & 3, ln = p & 31;
        int g = ln >> 2, tg = ln & 3;
        int m0 = mb*16 + g, r0 = kb*8 + tg;
        float4 v;
        #define GV(t,r) tf32rna(((r)&1) ? smim[t][(r)>>1] : smre[t][(r)>>1])
        v.x = GV(m0,   r0); v.y = GV(m0+8, r0);
        v.z = GV(m0, r0+4); v.w = GV(m0+8, r0+4);
        #undef GV
        GTP[p] = v;
    }
    __syncthreads();
    // phase 3: K[d] = Re(sum_n Ct*w^d)
    {
        float zr = cr, zi = ci;
        for (int d = 0; d < 64; ++d) {
            smre[d][n] = zr;
            float tt = zr*wr - zi*wi; zi = zr*wi + zi*wr; zr = tt;
        }
    }
    __syncthreads();
    {
        float s = 0.f;
        for (int q = 0; q < 64; ++q) s += smre[n][q];
        kv[n] = s;
    }
    __syncthreads();
    float dc = D[c];
    for (int p = n; p < 1024; p += 64) {
        int kb = 16 + (p >> 7), mb = (p >> 5) & 3, ln = p & 31;
        int g = ln >> 2, tg = ln & 3;
        int m0 = mb*16 + g, r0 = kb*8 + tg;
        float4 v;
        #define TV(t,r) tf32rna((((t) >= (r)-128) ? kv[(t)-((r)-128)] : 0.f) + (((t) == (r)-128) ? dc : 0.f))
        v.x = TV(m0,   r0); v.y = TV(m0+8, r0);
        v.z = TV(m0, r0+4); v.w = TV(m0+8, r0+4);
        #undef TV
        GTP[2048 + p] = v;
    }
}

// ---------------- fused SSM: v=x+pe -> B=Qt@V -> scan -> Y=[G|T]@[S0;V] -> gelu ----------------
// one CTA per (b,c); 128 threads = 4 warps as 2(m) x 2(n); smem: Vs 64x68 + Bs 128x68
#define SP 68
#define SMEMSZ ((64*SP + 128*SP)*4)

__global__ __launch_bounds__(128) void fused_kernel(const float* __restrict__ xin) {
    extern __shared__ float sm[];
    float* Vs = sm;                    // [64][SP]   V [j][k]
    float* Bs = sm + 64*SP;            // [128][SP]  B, then S0 [row][k]

    int bc = blockIdx.x;
    int c  = bc & (Hc - 1);
    int t  = threadIdx.x;
    int lane = t & 31, wrp = t >> 5;
    int gID = lane >> 2, tig = lane & 3;
    int wm = wrp & 1, wn = wrp >> 1;   // 2(m) x 2(n)
    int cnb = wn << 5;                 // n-col base (0 / 32)

    const float4* QtP = g_QtP + (size_t)c * 2048;
    const float4* GTP = g_GTP + (size_t)c * 3072;

    // ---- v = x + posenc, transposed into Vs[j][k] ----
    {
        int cax; const float* et;
        if (c < CH3)        { cax = 0; et = g_emb + c; }
        else if (c < 2*CH3) { cax = 1; et = g_emb + 16*CH3 + (c - CH3); }
        else                { cax = 2; et = g_emb + 32*CH3 + (c - 2*CH3); }
        const float* xp = xin + (size_t)bc * Lt;
        #pragma unroll
        for (int p = 0; p < 8; ++p) {
            int l = (t + p*128) << 2;
            float4 xv = *(const float4*)&xp[l];
            float p0, p1, p2, p3;
            if (cax == 0)      { float e = et[(l >> 8)*CH3];        p0 = p1 = p2 = p3 = e; }
            else if (cax == 1) { float e = et[((l >> 4) & 15)*CH3]; p0 = p1 = p2 = p3 = e; }
            else {
                int lw = l & 15;
                p0 = et[lw*CH3]; p1 = et[(lw+1)*CH3]; p2 = et[(lw+2)*CH3]; p3 = et[(lw+3)*CH3];
            }
            int j = l & 63, k = l >> 6;
            Vs[(j  )*SP + k] = tf32rna(xv.x + p0);
            Vs[(j+1)*SP + k] = tf32rna(xv.y + p1);
            Vs[(j+2)*SP + k] = tf32rna(xv.z + p2);
            Vs[(j+3)*SP + k] = tf32rna(xv.w + p3);
        }
    }
    __syncthreads();

    // ---- pass A: B[n][k] = sum_j Qt[j][n] * V[j][k] ----
    // warp (wm,wn): rows mh*64 + wm*32 + mb*16, cols wn*32 + nt*8
    #pragma unroll
    for (int mh = 0; mh < 2; ++mh) {
        float acc[2][4][4];
        #pragma unroll
        for (int mb = 0; mb < 2; ++mb)
            #pragma unroll
            for (int nt = 0; nt < 4; ++nt)
                #pragma unroll
                for (int r = 0; r < 4; ++r) acc[mb][nt][r] = 0.f;
        #pragma unroll
        for (int k8 = 0; k8 < 8; ++k8) {
            int kd = k8 << 3;
            float4 qf[2];
            #pragma unroll
            for (int mb = 0; mb < 2; ++mb)
                qf[mb] = QtP[(k8*8 + mh*4 + wm*2 + mb)*32 + lane];
            uint32_t b0[4], b1[4];
            #pragma unroll
            for (int nt = 0; nt < 4; ++nt) {
                int cn = cnb + (nt << 3) + gID;
                b0[nt] = __float_as_uint(Vs[(kd + tig    )*SP + cn]);
                b1[nt] = __float_as_uint(Vs[(kd + tig + 4)*SP + cn]);
            }
            #pragma unroll
            for (int mb = 0; mb < 2; ++mb) {
                uint32_t a0 = __float_as_uint(qf[mb].x), a1 = __float_as_uint(qf[mb].y);
                uint32_t a2 = __float_as_uint(qf[mb].z), a3 = __float_as_uint(qf[mb].w);
                #pragma unroll
                for (int nt = 0; nt < 4; ++nt)
                    MMA_TF32(acc[mb][nt], a0, a1, a2, a3, b0[nt], b1[nt]);
            }
        }
        #pragma unroll
        for (int mb = 0; mb < 2; ++mb) {
            int row0 = mh*64 + wm*32 + mb*16 + gID;
            #pragma unroll
            for (int nt = 0; nt < 4; ++nt) {
                int col = cnb + (nt << 3) + (tig << 1);
                Bs[row0*SP + col]         = acc[mb][nt][0];
                Bs[row0*SP + col + 1]     = acc[mb][nt][1];
                Bs[(row0+8)*SP + col]     = acc[mb][nt][2];
                Bs[(row0+8)*SP + col + 1] = acc[mb][nt][3];
            }
        }
    }
    __syncthreads();

    // ---- in-smem scan over 64 chunks: S0(k+1) = w^64*S0(k) + B(k); Bs := S0 (tf32) ----
    if (t < 64) {
        int nn = c*64 + t;
        float wr = g_wTre[nn], wi = g_wTim[nn];
        float* rr = &Bs[(2*t)*SP];
        float* ri = &Bs[(2*t + 1)*SP];
        float sr = 0.f, si = 0.f;
        #pragma unroll 8
        for (int k = 0; k < 64; ++k) {
            float br = rr[k], bi = ri[k];
            rr[k] = tf32rna(sr); ri[k] = tf32rna(si);
            float nr = fmaf(wr, sr, fmaf(-wi, si, br));
            si       = fmaf(wr, si, fmaf( wi, sr, bi));
            sr = nr;
        }
    }
    __syncthreads();

    // ---- pass C: Y[t][k] = sum_r GT[r][t] * X[r][k], X = [S0(128) ; V(64)] ----
    // warp (wm,wn): rows wm*32 + mb*16, cols wn*32 + nt*8
    float accC[2][4][4];
    #pragma unroll
    for (int mb = 0; mb < 2; ++mb)
        #pragma unroll
        for (int nt = 0; nt < 4; ++nt)
            #pragma unroll
            for (int r = 0; r < 4; ++r) accC[mb][nt][r] = 0.f;

    #pragma unroll
    for (int s = 0; s < 3; ++s) {
        const float* Bsrc = (s < 2) ? &Bs[s*64*SP] : Vs;
        #pragma unroll
        for (int k8 = 0; k8 < 8; ++k8) {
            int kd = k8 << 3;
            float4 gf[2];
            #pragma unroll
            for (int mb = 0; mb < 2; ++mb)
                gf[mb] = GTP[((s*8 + k8)*4 + wm*2 + mb)*32 + lane];
            uint32_t b0[4], b1[4];
            #pragma unroll
            for (int nt = 0; nt < 4; ++nt) {
                int cn = cnb + (nt << 3) + gID;
                b0[nt] = __float_as_uint(Bsrc[(kd + tig    )*SP + cn]);
                b1[nt] = __float_as_uint(Bsrc[(kd + tig + 4)*SP + cn]);
            }
            #pragma unroll
            for (int mb = 0; mb < 2; ++mb) {
                uint32_t a0 = __float_as_uint(gf[mb].x), a1 = __float_as_uint(gf[mb].y);
                uint32_t a2 = __float_as_uint(gf[mb].z), a3 = __float_as_uint(gf[mb].w);
                #pragma unroll
                for (int nt = 0; nt < 4; ++nt)
                    MMA_TF32(accC[mb][nt], a0, a1, a2, a3, b0[nt], b1[nt]);
            }
        }
    }

    // ---- epilogue: l = k*64 + t, gelu, tf32 round ----
    float* yp = g_yT + (size_t)bc * Lt;
    #pragma unroll
    for (int mb = 0; mb < 2; ++mb) {
        int t0 = wm*32 + mb*16 + gID;
        #pragma unroll
        for (int nt = 0; nt < 4; ++nt) {
            int k0 = cnb + (nt << 3) + (tig << 1);
            yp[(size_t)k0    *64 + t0    ] = tf32rna(gelu_f(accC[mb][nt][0]));
            yp[(size_t)(k0+1)*64 + t0    ] = tf32rna(gelu_f(accC[mb][nt][1]));
            yp[(size_t)k0    *64 + t0 + 8] = tf32rna(gelu_f(accC[mb][nt][2]));
            yp[(size_t)(k0+1)*64 + t0 + 8] = tf32rna(gelu_f(accC[mb][nt][3]));
        }
    }
}

// ---------------- final tf32 GEMM: out = Wp(frag) @ yT + bias ----------------
// tile 128(o) x 128(l), BK=16, 256 threads = 8 warps as 2(o) x 4(l)
__global__ __launch_bounds__(256, 2) void gemm_kernel(const float* __restrict__ bias,
                                                      float* __restrict__ out) {
    __shared__ float Ys[2][16][132];
    int b  = blockIdx.z;
    int oo = blockIdx.y << 7;
    int ll = blockIdx.x << 7;
    int t  = threadIdx.x;
    int lane = t & 31, wid = t >> 5;
    int wm = wid & 1, wn = wid >> 1;   // 2(o) x 4(l)
    int on = wn << 5;                  // 0,32,64,96
    int gID = lane >> 2, tig = lane & 3;

    int lr = t >> 4;
    int lc = (t & 15) << 2;
    const float* Yp = g_yT + ((size_t)b * Hc + lr) * Lt + ll + lc;
    int MbBase = (oo >> 4) + (wm << 2);   // 4 mb per warp

    float4 yv0 = *(const float4*)Yp;
    float4 yv1 = *(const float4*)(Yp + 64);

    float acc[4][4][4];
    #pragma unroll
    for (int mb = 0; mb < 4; ++mb)
        #pragma unroll
        for (int nt = 0; nt < 4; ++nt)
            #pragma unroll
            for (int r = 0; r < 4; ++r) acc[mb][nt][r] = 0.f;

    int buf = 0;
    for (int s = 0; s < Hc/16; ++s) {
        *(float4*)&Ys[buf][lr][lc]      = yv0;
        *(float4*)&Ys[buf][lr][lc + 64] = yv1;
        __syncthreads();
        if (s + 1 < Hc/16) {
            size_t ko = (size_t)(s + 1) * 16;
            yv0 = *(const float4*)(Yp + ko * Lt);
            yv1 = *(const float4*)(Yp + ko * Lt + 64);
        }
        #pragma unroll
        for (int k8i = 0; k8i < 2; ++k8i) {
            int k8 = k8i << 3;
            float4 af[4];
            #pragma unroll
            for (int mb = 0; mb < 4; ++mb)
                af[mb] = g_Wp[(size_t)((s*2 + k8i)*32 + MbBase + mb)*32 + lane];
            uint32_t bf[4][2];
            #pragma unroll
            for (int nt = 0; nt < 4; ++nt) {
                int cn = on + (nt << 3) + gID;
                bf[nt][0] = __float_as_uint(Ys[buf][k8 + tig    ][cn]);
                bf[nt][1] = __float_as_uint(Ys[buf][k8 + tig + 4][cn]);
            }
            #pragma unroll
            for (int mb = 0; mb < 4; ++mb) {
                uint32_t a0 = __float_as_uint(af[mb].x), a1 = __float_as_uint(af[mb].y);
                uint32_t a2 = __float_as_uint(af[mb].z), a3 = __float_as_uint(af[mb].w);
                #pragma unroll
                for (int nt = 0; nt < 4; ++nt)
                    MMA_TF32(acc[mb][nt], a0, a1, a2, a3, bf[nt][0], bf[nt][1]);
            }
        }
        buf ^= 1;
        __syncthreads();
    }

    #pragma unroll
    for (int mb = 0; mb < 4; ++mb) {
        int o0 = oo + wm*64 + mb*16 + gID;
        float b0 = __ldg(&bias[o0]);
        float b8 = __ldg(&bias[o0 + 8]);
        float* r0p = out + ((size_t)b * OUTc + o0)     * Lt + ll + on + (tig << 1);
        float* r8p = out + ((size_t)b * OUTc + o0 + 8) * Lt + ll + on + (tig << 1);
        #pragma unroll
        for (int nt = 0; nt < 4; ++nt) {
            *(float2*)(r0p + (nt << 3)) = make_float2(acc[mb][nt][0] + b0, acc[mb][nt][1] + b0);
            *(float2*)(r8p + (nt << 3)) = make_float2(acc[mb][nt][2] + b8, acc[mb][nt][3] + b8);
        }
    }
}

// ---------------- launch ----------------
extern "C" void kernel_launch(void* const* d_in, const int* in_sizes, int n_in,
                              void* d_out, int out_size) {
    const float* x      = (const float*)d_in[0];
    const float* log_dt = (const float*)d_in[1];
    const float* A_re   = (const float*)d_in[2];
    const float* A_im   = (const float*)d_in[3];
    const float* C_re   = (const float*)d_in[4];
    const float* C_im   = (const float*)d_in[5];
    const float* D      = (const float*)d_in[6];
    const float* W      = (const float*)d_in[7];
    const float* bias   = (const float*)d_in[8];
    float* out = (float*)d_out;

    cudaFuncSetAttribute(fused_kernel, cudaFuncAttributeMaxDynamicSharedMemorySize, SMEMSZ);

    int nprep = NWP + NCT + NEMB;
    prep_all_kernel<<<(nprep + 255)/256, 256>>>(W, log_dt, A_re, A_im, C_re, C_im);
    build_kernel<<<Hc, 64>>>(D);
    fused_kernel<<<BC, 128, SMEMSZ>>>(x);
    gemm_kernel<<<dim3(Lt/128, OUTc/128, BSz), 256>>>(bias, out);
}

// round 14
// speedup vs baseline: 1.0154x; 1.0154x over previous
#include <cuda_runtime.h>
#include <math.h>
#include <stdint.h>

#define Hc   1024
#define Nst  64
#define Lt   4096
#define OUTc 512
#define BSz  2
#define BC   (BSz*Hc)
#define CH3  342   // per-axis posenc channels

// ---------------- helpers ----------------
__device__ __forceinline__ float tf32rna(float v) {
    uint32_t u; asm("cvt.rna.tf32.f32 %0, %1;" : "=r"(u) : "f"(v));
    return __uint_as_float(u);
}
__device__ __forceinline__ float gelu_f(float s) {
    float a2 = 1.5957691216057308f * fmaf(0.044715f * s, s * s, s);
    float e  = __expf(a2);
    float th = 1.0f - __fdividef(2.0f, e + 1.0f);
    return 0.5f * s * (1.0f + th);
}
#define MMA_TF32(acc, a0,a1,a2,a3, b0,b1) \
    asm("mma.sync.aligned.m16n8k8.row.col.f32.tf32.tf32.f32 " \
        "{%0,%1,%2,%3},{%4,%5,%6,%7},{%8,%9},{%0,%1,%2,%3};" \
        : "+f"(acc[0]), "+f"(acc[1]), "+f"(acc[2]), "+f"(acc[3]) \
        : "r"(a0), "r"(a1), "r"(a2), "r"(a3), "r"(b0), "r"(b1))

// ---------------- scratch ----------------
__device__ float  g_yT[BC*Lt];          // gelu output, (b, c, l), tf32
__device__ float4 g_Wp [128*32*32];     // W fragment-packed: [kb][mb][lane]
__device__ float4 g_QtP[Hc*2048];       // per c: [kb0..7][mb0..7][lane]
__device__ float4 g_GTP[Hc*3072];       // per c: [kb0..23][mb0..3][lane]
__device__ float g_wre[Hc*Nst],  g_wim[Hc*Nst];
__device__ float g_wTre[Hc*Nst], g_wTim[Hc*Nst];   // w^64
__device__ float g_ctre[Hc*Nst], g_ctim[Hc*Nst];
__device__ float g_emb[3*16*CH3];

// ---------------- merged prep: W fragment-pack | discretize | emb ----------------
#define NWP (128*32*32)
#define NCT (Hc*Nst)
#define NEMB (3*16*CH3)

__global__ void prep_all_kernel(const float* __restrict__ W,
                                const float* __restrict__ log_dt,
                                const float* __restrict__ Are, const float* __restrict__ Aim,
                                const float* __restrict__ Cre, const float* __restrict__ Cim) {
    int idx = blockIdx.x * blockDim.x + threadIdx.x;
    if (idx < NWP) {
        int kb = idx >> 10;
        int mb = (idx >> 5) & 31;
        int ln = idx & 31;
        int g = ln >> 2, tg = ln & 3;
        int m0 = mb*16 + g, k0 = kb*8 + tg;
        float4 v;
        v.x = tf32rna(W[(size_t)k0*OUTc + m0]);
        v.y = tf32rna(W[(size_t)k0*OUTc + m0 + 8]);
        v.z = tf32rna(W[(size_t)(k0+4)*OUTc + m0]);
        v.w = tf32rna(W[(size_t)(k0+4)*OUTc + m0 + 8]);
        g_Wp[idx] = v;
        return;
    }
    int i2 = idx - NWP;
    if (i2 < NCT) {
        int c = i2 >> 6;
        double dt  = exp((double)log_dt[c]);
        double ar  = (double)Are[i2], ai = (double)Aim[i2];
        double dar = dt*ar, dai = dt*ai;
        double er  = exp(dar);
        double wr = er*cos(dai), wi = er*sin(dai);
        g_wre[i2] = (float)wr; g_wim[i2] = (float)wi;
        double erT = exp(64.0 * dar);
        g_wTre[i2] = (float)(erT*cos(64.0*dai));
        g_wTim[i2] = (float)(erT*sin(64.0*dai));
        double nr = wr - 1.0, ni = wi;
        double inv = 1.0 / (ar*ar + ai*ai);
        double qr = (nr*ar + ni*ai) * inv;
        double qi = (ni*ar - nr*ai) * inv;
        double cr = (double)Cre[i2], ci = (double)Cim[i2];
        g_ctre[i2] = (float)(2.0*(cr*qr - ci*qi));
        g_ctim[i2] = (float)(2.0*(cr*qi + ci*qr));
        return;
    }
    int i3 = i2 - NCT;
    if (i3 < NEMB) {
        int k   = i3 % CH3;
        int pos = (i3 / CH3) % 16;
        int i   = k >> 1;
        float freq = expf(-logf(10000.0f) * (float)(2*i) / (float)CH3);
        float arg  = (float)pos * freq;
        g_emb[i3] = (k & 1) ? cosf(arg) : sinf(arg);
    }
}

// ---------------- build QtP / GTP (fragment-packed) per channel ----------------
__global__ __launch_bounds__(64) void build_kernel(const float* __restrict__ D) {
    __shared__ float smre[64][65];
    __shared__ float smim[64][65];
    __shared__ float kv[64];
    int c = blockIdx.x;
    int n = threadIdx.x;
    int nn = c*64 + n;
    float wr = g_wre[nn], wi = g_wim[nn];
    float cr = g_ctre[nn], ci = g_ctim[nn];
    float4* QtP = g_QtP + (size_t)c * 2048;
    float4* GTP = g_GTP + (size_t)c * 3072;

    // phase 1: powers w^0..w^63 per state n
    {
        float pr = 1.f, pi = 0.f;
        for (int d = 0; d < 64; ++d) {
            smre[d][n] = pr; smim[d][n] = pi;
            float t = pr*wr - pi*wi; pi = pr*wi + pi*wr; pr = t;
        }
    }
    __syncthreads();
    for (int p = n; p < 2048; p += 64) {
        int kb = p >> 8, mb = (p >> 5) & 7, ln = p & 31;
        int g = ln >> 2, tg = ln & 3;
        int m0 = mb*16 + g, k0 = kb*8 + tg;
        float4 v;
        #define QV(m,k) tf32rna(((m)&1) ? smim[63-(k)][(m)>>1] : smre[63-(k)][(m)>>1])
        v.x = QV(m0,   k0); v.y = QV(m0+8, k0);
        v.z = QV(m0, k0+4); v.w = QV(m0+8, k0+4);
        #undef QV
        QtP[p] = v;
    }
    __syncthreads();
    // phase 2: z = Ct*w^{t+1}: smre[t][n]=Re, smim[t][n]=-Im
    {
        float zr = cr*wr - ci*wi, zi = cr*wi + ci*wr;
        for (int t = 0; t < 64; ++t) {
            smre[t][n] = zr; smim[t][n] = -zi;
            float tt = zr*wr - zi*wi; zi = zr*wi + zi*wr; zr = tt;
        }
    }
    __syncthreads();
    for (int p = n; p < 2048; p += 64) {
        int kb = p >> 7, mb = (p >> 5) & 3, ln = p & 31;
        int g = ln >> 2, tg = ln & 3;
        int m0 = mb*16 + g, r0 = kb*8 + tg;
        float4 v;
        #define GV(t,r) tf32rna(((r)&1) ? smim[t][(r)>>1] : smre[t][(r)>>1])
        v.x = GV(m0,   r0); v.y = GV(m0+8, r0);
        v.z = GV(m0, r0+4); v.w = GV(m0+8, r0+4);
        #undef GV
        GTP[p] = v;
    }
    __syncthreads();
    // phase 3: K[d] = Re(sum_n Ct*w^d)
    {
        float zr = cr, zi = ci;
        for (int d = 0; d < 64; ++d) {
            smre[d][n] = zr;
            float tt = zr*wr - zi*wi; zi = zr*wi + zi*wr; zr = tt;
        }
    }
    __syncthreads();
    {
        float s = 0.f;
        for (int q = 0; q < 64; ++q) s += smre[n][q];
        kv[n] = s;
    }
    __syncthreads();
    float dc = D[c];
    for (int p = n; p < 1024; p += 64) {
        int kb = 16 + (p >> 7), mb = (p >> 5) & 3, ln = p & 31;
        int g = ln >> 2, tg = ln & 3;
        int m0 = mb*16 + g, r0 = kb*8 + tg;
        float4 v;
        #define TV(t,r) tf32rna((((t) >= (r)-128) ? kv[(t)-((r)-128)] : 0.f) + (((t) == (r)-128) ? dc : 0.f))
        v.x = TV(m0,   r0); v.y = TV(m0+8, r0);
        v.z = TV(m0, r0+4); v.w = TV(m0+8, r0+4);
        #undef TV
        GTP[2048 + p] = v;
    }
}

// ---------------- fused SSM: v=x+pe -> B=Qt@V -> scan -> Y=[G|T]@[S0;V] -> gelu ----------------
// one CTA per (b,c); 128 threads = 4 warps as 2(m) x 2(n); smem: Vs 64x68 + Bs 128x68
#define SP 68
#define SMEMSZ ((64*SP + 128*SP)*4)

__global__ __launch_bounds__(128) void fused_kernel(const float* __restrict__ xin) {
    extern __shared__ float sm[];
    float* Vs = sm;                    // [64][SP]   V [j][k]
    float* Bs = sm + 64*SP;            // [128][SP]  B, then S0 [row][k]

    int bc = blockIdx.x;
    int c  = bc & (Hc - 1);
    int t  = threadIdx.x;
    int lane = t & 31, wrp = t >> 5;
    int gID = lane >> 2, tig = lane & 3;
    int wm = wrp & 1, wn = wrp >> 1;   // 2(m) x 2(n)
    int cnb = wn << 5;                 // n-col base (0 / 32)

    const float4* QtP = g_QtP + (size_t)c * 2048;
    const float4* GTP = g_GTP + (size_t)c * 3072;

    // ---- v = x + posenc, transposed into Vs[j][k] ----
    {
        int cax; const float* et;
        if (c < CH3)        { cax = 0; et = g_emb + c; }
        else if (c < 2*CH3) { cax = 1; et = g_emb + 16*CH3 + (c - CH3); }
        else                { cax = 2; et = g_emb + 32*CH3 + (c - 2*CH3); }
        const float* xp = xin + (size_t)bc * Lt;
        #pragma unroll
        for (int p = 0; p < 8; ++p) {
            int l = (t + p*128) << 2;
            float4 xv = *(const float4*)&xp[l];
            float p0, p1, p2, p3;
            if (cax == 0)      { float e = et[(l >> 8)*CH3];        p0 = p1 = p2 = p3 = e; }
            else if (cax == 1) { float e = et[((l >> 4) & 15)*CH3]; p0 = p1 = p2 = p3 = e; }
            else {
                int lw = l & 15;
                p0 = et[lw*CH3]; p1 = et[(lw+1)*CH3]; p2 = et[(lw+2)*CH3]; p3 = et[(lw+3)*CH3];
            }
            int j = l & 63, k = l >> 6;
            Vs[(j  )*SP + k] = tf32rna(xv.x + p0);
            Vs[(j+1)*SP + k] = tf32rna(xv.y + p1);
            Vs[(j+2)*SP + k] = tf32rna(xv.z + p2);
            Vs[(j+3)*SP + k] = tf32rna(xv.w + p3);
        }
    }
    __syncthreads();

    // ---- pass A: B[n][k] = sum_j Qt[j][n] * V[j][k] ----
    #pragma unroll
    for (int mh = 0; mh < 2; ++mh) {
        float acc[2][4][4];
        #pragma unroll
        for (int mb = 0; mb < 2; ++mb)
            #pragma unroll
            for (int nt = 0; nt < 4; ++nt)
                #pragma unroll
                for (int r = 0; r < 4; ++r) acc[mb][nt][r] = 0.f;
        #pragma unroll
        for (int k8 = 0; k8 < 8; ++k8) {
            int kd = k8 << 3;
            float4 qf[2];
            #pragma unroll
            for (int mb = 0; mb < 2; ++mb)
                qf[mb] = QtP[(k8*8 + mh*4 + wm*2 + mb)*32 + lane];
            uint32_t b0[4], b1[4];
            #pragma unroll
            for (int nt = 0; nt < 4; ++nt) {
                int cn = cnb + (nt << 3) + gID;
                b0[nt] = __float_as_uint(Vs[(kd + tig    )*SP + cn]);
                b1[nt] = __float_as_uint(Vs[(kd + tig + 4)*SP + cn]);
            }
            #pragma unroll
            for (int mb = 0; mb < 2; ++mb) {
                uint32_t a0 = __float_as_uint(qf[mb].x), a1 = __float_as_uint(qf[mb].y);
                uint32_t a2 = __float_as_uint(qf[mb].z), a3 = __float_as_uint(qf[mb].w);
                #pragma unroll
                for (int nt = 0; nt < 4; ++nt)
                    MMA_TF32(acc[mb][nt], a0, a1, a2, a3, b0[nt], b1[nt]);
            }
        }
        #pragma unroll
        for (int mb = 0; mb < 2; ++mb) {
            int row0 = mh*64 + wm*32 + mb*16 + gID;
            #pragma unroll
            for (int nt = 0; nt < 4; ++nt) {
                int col = cnb + (nt << 3) + (tig << 1);
                Bs[row0*SP + col]         = acc[mb][nt][0];
                Bs[row0*SP + col + 1]     = acc[mb][nt][1];
                Bs[(row0+8)*SP + col]     = acc[mb][nt][2];
                Bs[(row0+8)*SP + col + 1] = acc[mb][nt][3];
            }
        }
    }
    __syncthreads();

    // ---- in-smem scan over 64 chunks: S0(k+1) = w^64*S0(k) + B(k); Bs := S0 (tf32) ----
    if (t < 64) {
        int nn = c*64 + t;
        float wr = g_wTre[nn], wi = g_wTim[nn];
        float* rr = &Bs[(2*t)*SP];
        float* ri = &Bs[(2*t + 1)*SP];
        float sr = 0.f, si = 0.f;
        #pragma unroll 8
        for (int k = 0; k < 64; ++k) {
            float br = rr[k], bi = ri[k];
            rr[k] = tf32rna(sr); ri[k] = tf32rna(si);
            float nr = fmaf(wr, sr, fmaf(-wi, si, br));
            si       = fmaf(wr, si, fmaf( wi, sr, bi));
            sr = nr;
        }
    }
    __syncthreads();

    // ---- pass C: Y[t][k] = sum_r GT[r][t] * X[r][k], X = [S0(128) ; V(64)] ----
    float accC[2][4][4];
    #pragma unroll
    for (int mb = 0; mb < 2; ++mb)
        #pragma unroll
        for (int nt = 0; nt < 4; ++nt)
            #pragma unroll
            for (int r = 0; r < 4; ++r) accC[mb][nt][r] = 0.f;

    #pragma unroll
    for (int s = 0; s < 3; ++s) {
        const float* Bsrc = (s < 2) ? &Bs[s*64*SP] : Vs;
        #pragma unroll
        for (int k8 = 0; k8 < 8; ++k8) {
            int kd = k8 << 3;
            float4 gf[2];
            #pragma unroll
            for (int mb = 0; mb < 2; ++mb)
                gf[mb] = GTP[((s*8 + k8)*4 + wm*2 + mb)*32 + lane];
            uint32_t b0[4], b1[4];
            #pragma unroll
            for (int nt = 0; nt < 4; ++nt) {
                int cn = cnb + (nt << 3) + gID;
                b0[nt] = __float_as_uint(Bsrc[(kd + tig    )*SP + cn]);
                b1[nt] = __float_as_uint(Bsrc[(kd + tig + 4)*SP + cn]);
            }
            #pragma unroll
            for (int mb = 0; mb < 2; ++mb) {
                uint32_t a0 = __float_as_uint(gf[mb].x), a1 = __float_as_uint(gf[mb].y);
                uint32_t a2 = __float_as_uint(gf[mb].z), a3 = __float_as_uint(gf[mb].w);
                #pragma unroll
                for (int nt = 0; nt < 4; ++nt)
                    MMA_TF32(accC[mb][nt], a0, a1, a2, a3, b0[nt], b1[nt]);
            }
        }
    }

    // ---- epilogue: l = k*64 + t, gelu, tf32 round ----
    float* yp = g_yT + (size_t)bc * Lt;
    #pragma unroll
    for (int mb = 0; mb < 2; ++mb) {
        int t0 = wm*32 + mb*16 + gID;
        #pragma unroll
        for (int nt = 0; nt < 4; ++nt) {
            int k0 = cnb + (nt << 3) + (tig << 1);
            yp[(size_t)k0    *64 + t0    ] = tf32rna(gelu_f(accC[mb][nt][0]));
            yp[(size_t)(k0+1)*64 + t0    ] = tf32rna(gelu_f(accC[mb][nt][1]));
            yp[(size_t)k0    *64 + t0 + 8] = tf32rna(gelu_f(accC[mb][nt][2]));
            yp[(size_t)(k0+1)*64 + t0 + 8] = tf32rna(gelu_f(accC[mb][nt][3]));
        }
    }
}

// ---------------- final tf32 GEMM: out = Wp(frag) @ yT + bias ----------------
// tile 128(o) x 128(l), BK=16, 256 threads = 8 warps as 2(o) x 4(l)
// A-fragments software-pipelined: prefetch fb+1 while fb's 16 MMAs execute
__global__ __launch_bounds__(256, 2) void gemm_kernel(const float* __restrict__ bias,
                                                      float* __restrict__ out) {
    __shared__ float Ys[2][16][132];
    int b  = blockIdx.z;
    int oo = blockIdx.y << 7;
    int ll = blockIdx.x << 7;
    int t  = threadIdx.x;
    int lane = t & 31, wid = t >> 5;
    int wm = wid & 1, wn = wid >> 1;   // 2(o) x 4(l)
    int on = wn << 5;                  // 0,32,64,96
    int gID = lane >> 2, tig = lane & 3;

    int lr = t >> 4;
    int lc = (t & 15) << 2;
    const float* Yp = g_yT + ((size_t)b * Hc + lr) * Lt + ll + lc;
    const float4* WpBase = g_Wp + (size_t)((oo >> 4) + (wm << 2)) * 32 + lane;
    // frag block fb: address WpBase + fb*32*32 + mb*32

    float4 yv0 = *(const float4*)Yp;
    float4 yv1 = *(const float4*)(Yp + 64);

    float4 af[4], afn[4];
    #pragma unroll
    for (int mb = 0; mb < 4; ++mb)
        af[mb] = WpBase[(size_t)mb * 32];

    float acc[4][4][4];
    #pragma unroll
    for (int mb = 0; mb < 4; ++mb)
        #pragma unroll
        for (int nt = 0; nt < 4; ++nt)
            #pragma unroll
            for (int r = 0; r < 4; ++r) acc[mb][nt][r] = 0.f;

    int buf = 0;
    for (int s = 0; s < Hc/16; ++s) {
        *(float4*)&Ys[buf][lr][lc]      = yv0;
        *(float4*)&Ys[buf][lr][lc + 64] = yv1;
        __syncthreads();
        if (s + 1 < Hc/16) {
            size_t ko = (size_t)(s + 1) * 16;
            yv0 = *(const float4*)(Yp + ko * Lt);
            yv1 = *(const float4*)(Yp + ko * Lt + 64);
        }
        #pragma unroll
        for (int k8i = 0; k8i < 2; ++k8i) {
            int fb = s*2 + k8i;
            // prefetch next frag block while computing this one
            if (fb + 1 < 128) {
                #pragma unroll
                for (int mb = 0; mb < 4; ++mb)
                    afn[mb] = WpBase[(size_t)(fb + 1) * 1024 + (size_t)mb * 32];
            }
            int k8 = k8i << 3;
            uint32_t bf[4][2];
            #pragma unroll
            for (int nt = 0; nt < 4; ++nt) {
                int cn = on + (nt << 3) + gID;
                bf[nt][0] = __float_as_uint(Ys[buf][k8 + tig    ][cn]);
                bf[nt][1] = __float_as_uint(Ys[buf][k8 + tig + 4][cn]);
            }
            #pragma unroll
            for (int mb = 0; mb < 4; ++mb) {
                uint32_t a0 = __float_as_uint(af[mb].x), a1 = __float_as_uint(af[mb].y);
                uint32_t a2 = __float_as_uint(af[mb].z), a3 = __float_as_uint(af[mb].w);
                #pragma unroll
                for (int nt = 0; nt < 4; ++nt)
                    MMA_TF32(acc[mb][nt], a0, a1, a2, a3, bf[nt][0], bf[nt][1]);
            }
            #pragma unroll
            for (int mb = 0; mb < 4; ++mb) af[mb] = afn[mb];
        }
        buf ^= 1;
        __syncthreads();
    }

    #pragma unroll
    for (int mb = 0; mb < 4; ++mb) {
        int o0 = oo + wm*64 + mb*16 + gID;
        float b0 = __ldg(&bias[o0]);
        float b8 = __ldg(&bias[o0 + 8]);
        float* r0p = out + ((size_t)b * OUTc + o0)     * Lt + ll + on + (tig << 1);
        float* r8p = out + ((size_t)b * OUTc + o0 + 8) * Lt + ll + on + (tig << 1);
        #pragma unroll
        for (int nt = 0; nt < 4; ++nt) {
            *(float2*)(r0p + (nt << 3)) = make_float2(acc[mb][nt][0] + b0, acc[mb][nt][1] + b0);
            *(float2*)(r8p + (nt << 3)) = make_float2(acc[mb][nt][2] + b8, acc[mb][nt][3] + b8);
        }
    }
}

// ---------------- launch ----------------
extern "C" void kernel_launch(void* const* d_in, const int* in_sizes, int n_in,
                              void* d_out, int out_size) {
    const float* x      = (const float*)d_in[0];
    const float* log_dt = (const float*)d_in[1];
    const float* A_re   = (const float*)d_in[2];
    const float* A_im   = (const float*)d_in[3];
    const float* C_re   = (const float*)d_in[4];
    const float* C_im   = (const float*)d_in[5];
    const float* D      = (const float*)d_in[6];
    const float* W      = (const float*)d_in[7];
    const float* bias   = (const float*)d_in[8];
    float* out = (float*)d_out;

    cudaFuncSetAttribute(fused_kernel, cudaFuncAttributeMaxDynamicSharedMemorySize, SMEMSZ);

    int nprep = NWP + NCT + NEMB;
    prep_all_kernel<<<(nprep + 255)/256, 256>>>(W, log_dt, A_re, A_im, C_re, C_im);
    build_kernel<<<Hc, 64>>>(D);
    fused_kernel<<<BC, 128, SMEMSZ>>>(x);
    gemm_kernel<<<dim3(Lt/128, OUTc/128, BSz), 256>>>(bias, out);
}

// round 15
// speedup vs baseline: 1.1009x; 1.0842x over previous
#include <cuda_runtime.h>
#include <math.h>
#include <stdint.h>

#define Hc   1024
#define Nst  64
#define Lt   4096
#define OUTc 512
#define BSz  2
#define BC   (BSz*Hc)
#define CH3  342   // per-axis posenc channels

// ---------------- helpers ----------------
__device__ __forceinline__ float tf32rna(float v) {
    uint32_t u; asm("cvt.rna.tf32.f32 %0, %1;" : "=r"(u) : "f"(v));
    return __uint_as_float(u);
}
__device__ __forceinline__ float gelu_f(float s) {
    float a2 = 1.5957691216057308f * fmaf(0.044715f * s, s * s, s);
    float e  = __expf(a2);
    float th = 1.0f - __fdividef(2.0f, e + 1.0f);
    return 0.5f * s * (1.0f + th);
}
#define MMA_TF32(acc, a0,a1,a2,a3, b0,b1) \
    asm("mma.sync.aligned.m16n8k8.row.col.f32.tf32.tf32.f32 " \
        "{%0,%1,%2,%3},{%4,%5,%6,%7},{%8,%9},{%0,%1,%2,%3};" \
        : "+f"(acc[0]), "+f"(acc[1]), "+f"(acc[2]), "+f"(acc[3]) \
        : "r"(a0), "r"(a1), "r"(a2), "r"(a3), "r"(b0), "r"(b1))

// ---------------- scratch ----------------
__device__ float  g_yT[BC*Lt];          // gelu output, (b, c, l), tf32
__device__ float4 g_Wp [128*32*32];     // W fragment-packed: [kb][mb][lane]
__device__ float4 g_QtP[Hc*2048];       // per c: [kb0..7][mb0..7][lane]
__device__ float4 g_GTP[Hc*3072];       // per c: [kb0..23][mb0..3][lane]
__device__ float g_wre[Hc*Nst],  g_wim[Hc*Nst];
__device__ float g_wTre[Hc*Nst], g_wTim[Hc*Nst];   // w^64
__device__ float g_ctre[Hc*Nst], g_ctim[Hc*Nst];
__device__ float g_emb[3*16*CH3];

// ---------------- merged prep: W fragment-pack | discretize | emb ----------------
#define NWP (128*32*32)
#define NCT (Hc*Nst)
#define NEMB (3*16*CH3)

__global__ void prep_all_kernel(const float* __restrict__ W,
                                const float* __restrict__ log_dt,
                                const float* __restrict__ Are, const float* __restrict__ Aim,
                                const float* __restrict__ Cre, const float* __restrict__ Cim) {
    int idx = blockIdx.x * blockDim.x + threadIdx.x;
    if (idx < NWP) {
        int kb = idx >> 10;
        int mb = (idx >> 5) & 31;
        int ln = idx & 31;
        int g = ln >> 2, tg = ln & 3;
        int m0 = mb*16 + g, k0 = kb*8 + tg;
        float4 v;
        v.x = tf32rna(W[(size_t)k0*OUTc + m0]);
        v.y = tf32rna(W[(size_t)k0*OUTc + m0 + 8]);
        v.z = tf32rna(W[(size_t)(k0+4)*OUTc + m0]);
        v.w = tf32rna(W[(size_t)(k0+4)*OUTc + m0 + 8]);
        g_Wp[idx] = v;
        return;
    }
    int i2 = idx - NWP;
    if (i2 < NCT) {
        int c = i2 >> 6;
        double dt  = exp((double)log_dt[c]);
        double ar  = (double)Are[i2], ai = (double)Aim[i2];
        double dar = dt*ar, dai = dt*ai;
        double er  = exp(dar);
        double wr = er*cos(dai), wi = er*sin(dai);
        g_wre[i2] = (float)wr; g_wim[i2] = (float)wi;
        double erT = exp(64.0 * dar);
        g_wTre[i2] = (float)(erT*cos(64.0*dai));
        g_wTim[i2] = (float)(erT*sin(64.0*dai));
        double nr = wr - 1.0, ni = wi;
        double inv = 1.0 / (ar*ar + ai*ai);
        double qr = (nr*ar + ni*ai) * inv;
        double qi = (ni*ar - nr*ai) * inv;
        double cr = (double)Cre[i2], ci = (double)Cim[i2];
        g_ctre[i2] = (float)(2.0*(cr*qr - ci*qi));
        g_ctim[i2] = (float)(2.0*(cr*qi + ci*qr));
        return;
    }
    int i3 = i2 - NCT;
    if (i3 < NEMB) {
        int k   = i3 % CH3;
        int pos = (i3 / CH3) % 16;
        int i   = k >> 1;
        float freq = expf(-logf(10000.0f) * (float)(2*i) / (float)CH3);
        float arg  = (float)pos * freq;
        g_emb[i3] = (k & 1) ? cosf(arg) : sinf(arg);
    }
}

// ---------------- build QtP / GTP (fragment-packed) per channel ----------------
__global__ __launch_bounds__(64) void build_kernel(const float* __restrict__ D) {
    __shared__ float smre[64][65];
    __shared__ float smim[64][65];
    __shared__ float kv[64];
    int c = blockIdx.x;
    int n = threadIdx.x;
    int nn = c*64 + n;
    float wr = g_wre[nn], wi = g_wim[nn];
    float cr = g_ctre[nn], ci = g_ctim[nn];
    float4* QtP = g_QtP + (size_t)c * 2048;
    float4* GTP = g_GTP + (size_t)c * 3072;

    // phase 1: powers w^0..w^63 per state n
    {
        float pr = 1.f, pi = 0.f;
        for (int d = 0; d < 64; ++d) {
            smre[d][n] = pr; smim[d][n] = pi;
            float t = pr*wr - pi*wi; pi = pr*wi + pi*wr; pr = t;
        }
    }
    __syncthreads();
    for (int p = n; p < 2048; p += 64) {
        int kb = p >> 8, mb = (p >> 5) & 7, ln = p & 31;
        int g = ln >> 2, tg = ln & 3;
        int m0 = mb*16 + g, k0 = kb*8 + tg;
        float4 v;
        #define QV(m,k) tf32rna(((m)&1) ? smim[63-(k)][(m)>>1] : smre[63-(k)][(m)>>1])
        v.x = QV(m0,   k0); v.y = QV(m0+8, k0);
        v.z = QV(m0, k0+4); v.w = QV(m0+8, k0+4);
        #undef QV
        QtP[p] = v;
    }
    __syncthreads();
    // phase 2: z = Ct*w^{t+1}: smre[t][n]=Re, smim[t][n]=-Im
    {
        float zr = cr*wr - ci*wi, zi = cr*wi + ci*wr;
        for (int t = 0; t < 64; ++t) {
            smre[t][n] = zr; smim[t][n] = -zi;
            float tt = zr*wr - zi*wi; zi = zr*wi + zi*wr; zr = tt;
        }
    }
    __syncthreads();
    for (int p = n; p < 2048; p += 64) {
        int kb = p >> 7, mb = (p >> 5) & 3, ln = p & 31;
        int g = ln >> 2, tg = ln & 3;
        int m0 = mb*16 + g, r0 = kb*8 + tg;
        float4 v;
        #define GV(t,r) tf32rna(((r)&1) ? smim[t][(r)>>1] : smre[t][(r)>>1])
        v.x = GV(m0,   r0); v.y = GV(m0+8, r0);
        v.z = GV(m0, r0+4); v.w = GV(m0+8, r0+4);
        #undef GV
        GTP[p] = v;
    }
    __syncthreads();
    // phase 3: K[d] = Re(sum_n Ct*w^d)
    {
        float zr = cr, zi = ci;
        for (int d = 0; d < 64; ++d) {
            smre[d][n] = zr;
            float tt = zr*wr - zi*wi; zi = zr*wi + zi*wr; zr = tt;
        }
    }
    __syncthreads();
    {
        float s = 0.f;
        for (int q = 0; q < 64; ++q) s += smre[n][q];
        kv[n] = s;
    }
    __syncthreads();
    float dc = D[c];
    for (int p = n; p < 1024; p += 64) {
        int kb = 16 + (p >> 7), mb = (p >> 5) & 3, ln = p & 31;
        int g = ln >> 2, tg = ln & 3;
        int m0 = mb*16 + g, r0 = kb*8 + tg;
        float4 v;
        #define TV(t,r) tf32rna((((t) >= (r)-128) ? kv[(t)-((r)-128)] : 0.f) + (((t) == (r)-128) ? dc : 0.f))
        v.x = TV(m0,   r0); v.y = TV(m0+8, r0);
        v.z = TV(m0, r0+4); v.w = TV(m0+8, r0+4);
        #undef TV
        GTP[2048 + p] = v;
    }
}

// ---------------- fused SSM: v=x+pe -> B=Qt@V -> scan -> Y=[G|T]@[S0;V] -> gelu ----------------
// one CTA per (b,c); 128 threads = 4 warps as 2(m) x 2(n); smem: Vs 64x68 + Bs 128x68
#define SP 68
#define SMEMSZ ((64*SP + 128*SP)*4)

__global__ __launch_bounds__(128) void fused_kernel(const float* __restrict__ xin) {
    extern __shared__ float sm[];
    float* Vs = sm;                    // [64][SP]   V [j][k]
    float* Bs = sm + 64*SP;            // [128][SP]  B, then S0 [row][k]

    int bc = blockIdx.x;
    int c  = bc & (Hc - 1);
    int t  = threadIdx.x;
    int lane = t & 31, wrp = t >> 5;
    int gID = lane >> 2, tig = lane & 3;
    int wm = wrp & 1, wn = wrp >> 1;   // 2(m) x 2(n)
    int cnb = wn << 5;                 // n-col base (0 / 32)

    const float4* QtP = g_QtP + (size_t)c * 2048;
    const float4* GTP = g_GTP + (size_t)c * 3072;

    // ---- v = x + posenc, transposed into Vs[j][k] ----
    {
        int cax; const float* et;
        if (c < CH3)        { cax = 0; et = g_emb + c; }
        else if (c < 2*CH3) { cax = 1; et = g_emb + 16*CH3 + (c - CH3); }
        else                { cax = 2; et = g_emb + 32*CH3 + (c - 2*CH3); }
        const float* xp = xin + (size_t)bc * Lt;
        #pragma unroll
        for (int p = 0; p < 8; ++p) {
            int l = (t + p*128) << 2;
            float4 xv = *(const float4*)&xp[l];
            float p0, p1, p2, p3;
            if (cax == 0)      { float e = et[(l >> 8)*CH3];        p0 = p1 = p2 = p3 = e; }
            else if (cax == 1) { float e = et[((l >> 4) & 15)*CH3]; p0 = p1 = p2 = p3 = e; }
            else {
                int lw = l & 15;
                p0 = et[lw*CH3]; p1 = et[(lw+1)*CH3]; p2 = et[(lw+2)*CH3]; p3 = et[(lw+3)*CH3];
            }
            int j = l & 63, k = l >> 6;
            Vs[(j  )*SP + k] = tf32rna(xv.x + p0);
            Vs[(j+1)*SP + k] = tf32rna(xv.y + p1);
            Vs[(j+2)*SP + k] = tf32rna(xv.z + p2);
            Vs[(j+3)*SP + k] = tf32rna(xv.w + p3);
        }
    }
    __syncthreads();

    // ---- pass A: B[n][k] = sum_j Qt[j][n] * V[j][k] ----
    #pragma unroll
    for (int mh = 0; mh < 2; ++mh) {
        float acc[2][4][4];
        #pragma unroll
        for (int mb = 0; mb < 2; ++mb)
            #pragma unroll
            for (int nt = 0; nt < 4; ++nt)
                #pragma unroll
                for (int r = 0; r < 4; ++r) acc[mb][nt][r] = 0.f;
        #pragma unroll
        for (int k8 = 0; k8 < 8; ++k8) {
            int kd = k8 << 3;
            float4 qf[2];
            #pragma unroll
            for (int mb = 0; mb < 2; ++mb)
                qf[mb] = QtP[(k8*8 + mh*4 + wm*2 + mb)*32 + lane];
            uint32_t b0[4], b1[4];
            #pragma unroll
            for (int nt = 0; nt < 4; ++nt) {
                int cn = cnb + (nt << 3) + gID;
                b0[nt] = __float_as_uint(Vs[(kd + tig    )*SP + cn]);
                b1[nt] = __float_as_uint(Vs[(kd + tig + 4)*SP + cn]);
            }
            #pragma unroll
            for (int mb = 0; mb < 2; ++mb) {
                uint32_t a0 = __float_as_uint(qf[mb].x), a1 = __float_as_uint(qf[mb].y);
                uint32_t a2 = __float_as_uint(qf[mb].z), a3 = __float_as_uint(qf[mb].w);
                #pragma unroll
                for (int nt = 0; nt < 4; ++nt)
                    MMA_TF32(acc[mb][nt], a0, a1, a2, a3, b0[nt], b1[nt]);
            }
        }
        #pragma unroll
        for (int mb = 0; mb < 2; ++mb) {
            int row0 = mh*64 + wm*32 + mb*16 + gID;
            #pragma unroll
            for (int nt = 0; nt < 4; ++nt) {
                int col = cnb + (nt << 3) + (tig << 1);
                Bs[row0*SP + col]         = acc[mb][nt][0];
                Bs[row0*SP + col + 1]     = acc[mb][nt][1];
                Bs[(row0+8)*SP + col]     = acc[mb][nt][2];
                Bs[(row0+8)*SP + col + 1] = acc[mb][nt][3];
            }
        }
    }
    __syncthreads();

    // ---- in-smem scan over 64 chunks: S0(k+1) = w^64*S0(k) + B(k); Bs := S0 (tf32) ----
    if (t < 64) {
        int nn = c*64 + t;
        float wr = g_wTre[nn], wi = g_wTim[nn];
        float* rr = &Bs[(2*t)*SP];
        float* ri = &Bs[(2*t + 1)*SP];
        float sr = 0.f, si = 0.f;
        #pragma unroll 8
        for (int k = 0; k < 64; ++k) {
            float br = rr[k], bi = ri[k];
            rr[k] = tf32rna(sr); ri[k] = tf32rna(si);
            float nr = fmaf(wr, sr, fmaf(-wi, si, br));
            si       = fmaf(wr, si, fmaf( wi, sr, bi));
            sr = nr;
        }
    }
    __syncthreads();

    // ---- pass C: Y[t][k] = sum_r GT[r][t] * X[r][k], X = [S0(128) ; V(64)] ----
    float accC[2][4][4];
    #pragma unroll
    for (int mb = 0; mb < 2; ++mb)
        #pragma unroll
        for (int nt = 0; nt < 4; ++nt)
            #pragma unroll
            for (int r = 0; r < 4; ++r) accC[mb][nt][r] = 0.f;

    #pragma unroll
    for (int s = 0; s < 3; ++s) {
        const float* Bsrc = (s < 2) ? &Bs[s*64*SP] : Vs;
        #pragma unroll
        for (int k8 = 0; k8 < 8; ++k8) {
            int kd = k8 << 3;
            float4 gf[2];
            #pragma unroll
            for (int mb = 0; mb < 2; ++mb)
                gf[mb] = GTP[((s*8 + k8)*4 + wm*2 + mb)*32 + lane];
            uint32_t b0[4], b1[4];
            #pragma unroll
            for (int nt = 0; nt < 4; ++nt) {
                int cn = cnb + (nt << 3) + gID;
                b0[nt] = __float_as_uint(Bsrc[(kd + tig    )*SP + cn]);
                b1[nt] = __float_as_uint(Bsrc[(kd + tig + 4)*SP + cn]);
            }
            #pragma unroll
            for (int mb = 0; mb < 2; ++mb) {
                uint32_t a0 = __float_as_uint(gf[mb].x), a1 = __float_as_uint(gf[mb].y);
                uint32_t a2 = __float_as_uint(gf[mb].z), a3 = __float_as_uint(gf[mb].w);
                #pragma unroll
                for (int nt = 0; nt < 4; ++nt)
                    MMA_TF32(accC[mb][nt], a0, a1, a2, a3, b0[nt], b1[nt]);
            }
        }
    }

    // ---- epilogue: l = k*64 + t, gelu, tf32 round ----
    float* yp = g_yT + (size_t)bc * Lt;
    #pragma unroll
    for (int mb = 0; mb < 2; ++mb) {
        int t0 = wm*32 + mb*16 + gID;
        #pragma unroll
        for (int nt = 0; nt < 4; ++nt) {
            int k0 = cnb + (nt << 3) + (tig << 1);
            yp[(size_t)k0    *64 + t0    ] = tf32rna(gelu_f(accC[mb][nt][0]));
            yp[(size_t)(k0+1)*64 + t0    ] = tf32rna(gelu_f(accC[mb][nt][1]));
            yp[(size_t)k0    *64 + t0 + 8] = tf32rna(gelu_f(accC[mb][nt][2]));
            yp[(size_t)(k0+1)*64 + t0 + 8] = tf32rna(gelu_f(accC[mb][nt][3]));
        }
    }
}

// ---------------- final tf32 GEMM (R12-validated): out = Wp(frag) @ yT + bias ----------------
// tile 128(o) x 128(l), BK=16, 256 threads = 8 warps as 4(o) x 2(l); A frags double-buffered
__global__ __launch_bounds__(256, 2) void gemm_kernel(const float* __restrict__ bias,
                                                      float* __restrict__ out) {
    __shared__ float Ys[2][16][132];
    int b  = blockIdx.z;
    int oo = blockIdx.y << 7;
    int ll = blockIdx.x << 7;
    int t  = threadIdx.x;
    int lane = t & 31, wid = t >> 5;
    int om = (wid & 3) << 5;
    int on = (wid >> 2) << 6;
    int gID = lane >> 2, tig = lane & 3;

    int lr = t >> 4;
    int lc = (t & 15) << 2;
    const float* Yp = g_yT + ((size_t)b * Hc + lr) * Lt + ll + lc;
    int MbBase = (oo >> 4) + ((wid & 3) << 1);

    float4 yv0 = *(const float4*)Yp;
    float4 yv1 = *(const float4*)(Yp + 64);

    float4 af[2][2], afn[2][2];
    #pragma unroll
    for (int k8i = 0; k8i < 2; ++k8i)
        #pragma unroll
        for (int mt = 0; mt < 2; ++mt)
            af[k8i][mt] = g_Wp[(size_t)(k8i*32 + MbBase + mt)*32 + lane];

    float acc[2][8][4];
    #pragma unroll
    for (int mt = 0; mt < 2; ++mt)
        #pragma unroll
        for (int nt = 0; nt < 8; ++nt)
            #pragma unroll
            for (int r = 0; r < 4; ++r) acc[mt][nt][r] = 0.f;

    int buf = 0;
    for (int s = 0; s < Hc/16; ++s) {
        *(float4*)&Ys[buf][lr][lc]      = yv0;
        *(float4*)&Ys[buf][lr][lc + 64] = yv1;
        __syncthreads();
        if (s + 1 < Hc/16) {
            size_t ko = (size_t)(s + 1) * 16;
            yv0 = *(const float4*)(Yp + ko * Lt);
            yv1 = *(const float4*)(Yp + ko * Lt + 64);
            #pragma unroll
            for (int k8i = 0; k8i < 2; ++k8i)
                #pragma unroll
                for (int mt = 0; mt < 2; ++mt)
                    afn[k8i][mt] = g_Wp[(size_t)(((s+1)*2 + k8i)*32 + MbBase + mt)*32 + lane];
        }
        #pragma unroll
        for (int k8i = 0; k8i < 2; ++k8i) {
            int k8 = k8i << 3;
            uint32_t bf[8][2];
            #pragma unroll
            for (int nt = 0; nt < 8; ++nt) {
                int cn = on + (nt << 3) + gID;
                bf[nt][0] = __float_as_uint(Ys[buf][k8 + tig    ][cn]);
                bf[nt][1] = __float_as_uint(Ys[buf][k8 + tig + 4][cn]);
            }
            #pragma unroll
            for (int mt = 0; mt < 2; ++mt) {
                uint32_t a0 = __float_as_uint(af[k8i][mt].x), a1 = __float_as_uint(af[k8i][mt].y);
                uint32_t a2 = __float_as_uint(af[k8i][mt].z), a3 = __float_as_uint(af[k8i][mt].w);
                #pragma unroll
                for (int nt = 0; nt < 8; ++nt)
                    MMA_TF32(acc[mt][nt], a0, a1, a2, a3, bf[nt][0], bf[nt][1]);
            }
        }
        #pragma unroll
        for (int k8i = 0; k8i < 2; ++k8i)
            #pragma unroll
            for (int mt = 0; mt < 2; ++mt)
                af[k8i][mt] = afn[k8i][mt];
        buf ^= 1;
        __syncthreads();
    }

    #pragma unroll
    for (int mt = 0; mt < 2; ++mt) {
        int o0 = oo + om + (mt << 4) + gID;
        float b0 = __ldg(&bias[o0]);
        float b8 = __ldg(&bias[o0 + 8]);
        float* r0p = out + ((size_t)b * OUTc + o0)     * Lt + ll + on + (tig << 1);
        float* r8p = out + ((size_t)b * OUTc + o0 + 8) * Lt + ll + on + (tig << 1);
        #pragma unroll
        for (int nt = 0; nt < 8; ++nt) {
            *(float2*)(r0p + (nt << 3)) = make_float2(acc[mt][nt][0] + b0, acc[mt][nt][1] + b0);
            *(float2*)(r8p + (nt << 3)) = make_float2(acc[mt][nt][2] + b8, acc[mt][nt][3] + b8);
        }
    }
}

// ---------------- launch ----------------
extern "C" void kernel_launch(void* const* d_in, const int* in_sizes, int n_in,
                              void* d_out, int out_size) {
    const float* x      = (const float*)d_in[0];
    const float* log_dt = (const float*)d_in[1];
    const float* A_re   = (const float*)d_in[2];
    const float* A_im   = (const float*)d_in[3];
    const float* C_re   = (const float*)d_in[4];
    const float* C_im   = (const float*)d_in[5];
    const float* D      = (const float*)d_in[6];
    const float* W      = (const float*)d_in[7];
    const float* bias   = (const float*)d_in[8];
    float* out = (float*)d_out;

    cudaFuncSetAttribute(fused_kernel, cudaFuncAttributeMaxDynamicSharedMemorySize, SMEMSZ);

    int nprep = NWP + NCT + NEMB;
    prep_all_kernel<<<(nprep + 255)/256, 256>>>(W, log_dt, A_re, A_im, C_re, C_im);
    build_kernel<<<Hc, 64>>>(D);
    fused_kernel<<<BC, 128, SMEMSZ>>>(x);
    gemm_kernel<<<dim3(Lt/128, OUTc/128, BSz), 256>>>(bias, out);
}

// round 16
// speedup vs baseline: 1.3233x; 1.2020x over previous
#include <cuda_runtime.h>
#include <math.h>
#include <stdint.h>

#define Hc   1024
#define Nst  64
#define Lt   4096
#define OUTc 512
#define BSz  2
#define BC   (BSz*Hc)
#define CH3  342   // per-axis posenc channels

// ---------------- helpers ----------------
__device__ __forceinline__ float tf32rna(float v) {
    uint32_t u; asm("cvt.rna.tf32.f32 %0, %1;" : "=r"(u) : "f"(v));
    return __uint_as_float(u);
}
__device__ __forceinline__ float gelu_f(float s) {
    float a2 = 1.5957691216057308f * fmaf(0.044715f * s, s * s, s);
    float e  = __expf(a2);
    float th = 1.0f - __fdividef(2.0f, e + 1.0f);
    return 0.5f * s * (1.0f + th);
}
#define MMA_TF32(acc, a0,a1,a2,a3, b0,b1) \
    asm("mma.sync.aligned.m16n8k8.row.col.f32.tf32.tf32.f32 " \
        "{%0,%1,%2,%3},{%4,%5,%6,%7},{%8,%9},{%0,%1,%2,%3};" \
        : "+f"(acc[0]), "+f"(acc[1]), "+f"(acc[2]), "+f"(acc[3]) \
        : "r"(a0), "r"(a1), "r"(a2), "r"(a3), "r"(b0), "r"(b1))

// ---------------- scratch ----------------
__device__ float  g_yT[BC*Lt];          // gelu output, (b, c, l), tf32
__device__ float4 g_Wp [128*32*32];     // W fragment-packed: [kb][mb][lane]
__device__ float4 g_QtP[Hc*2048];       // per c: [kb0..7][mb0..7][lane]
__device__ float4 g_GTP[Hc*3072];       // per c: [kb0..23][mb0..3][lane]
__device__ float g_wre[Hc*Nst],  g_wim[Hc*Nst];
__device__ float g_wTre[Hc*Nst], g_wTim[Hc*Nst];   // w^64
__device__ float g_ctre[Hc*Nst], g_ctim[Hc*Nst];
__device__ float g_emb[3*16*CH3];

// ---------------- merged prep: W fragment-pack | discretize | emb ----------------
#define NWP (128*32*32)
#define NCT (Hc*Nst)
#define NEMB (3*16*CH3)

__global__ void prep_all_kernel(const float* __restrict__ W,
                                const float* __restrict__ log_dt,
                                const float* __restrict__ Are, const float* __restrict__ Aim,
                                const float* __restrict__ Cre, const float* __restrict__ Cim) {
    int idx = blockIdx.x * blockDim.x + threadIdx.x;
    if (idx < NWP) {
        int kb = idx >> 10;
        int mb = (idx >> 5) & 31;
        int ln = idx & 31;
        int g = ln >> 2, tg = ln & 3;
        int m0 = mb*16 + g, k0 = kb*8 + tg;
        float4 v;
        v.x = tf32rna(W[(size_t)k0*OUTc + m0]);
        v.y = tf32rna(W[(size_t)k0*OUTc + m0 + 8]);
        v.z = tf32rna(W[(size_t)(k0+4)*OUTc + m0]);
        v.w = tf32rna(W[(size_t)(k0+4)*OUTc + m0 + 8]);
        g_Wp[idx] = v;
        return;
    }
    int i2 = idx - NWP;
    if (i2 < NCT) {
        int c = i2 >> 6;
        double dt  = exp((double)log_dt[c]);
        double ar  = (double)Are[i2], ai = (double)Aim[i2];
        double dar = dt*ar, dai = dt*ai;
        double er  = exp(dar);
        double wr = er*cos(dai), wi = er*sin(dai);
        g_wre[i2] = (float)wr; g_wim[i2] = (float)wi;
        double erT = exp(64.0 * dar);
        g_wTre[i2] = (float)(erT*cos(64.0*dai));
        g_wTim[i2] = (float)(erT*sin(64.0*dai));
        double nr = wr - 1.0, ni = wi;
        double inv = 1.0 / (ar*ar + ai*ai);
        double qr = (nr*ar + ni*ai) * inv;
        double qi = (ni*ar - nr*ai) * inv;
        double cr = (double)Cre[i2], ci = (double)Cim[i2];
        g_ctre[i2] = (float)(2.0*(cr*qr - ci*qi));
        g_ctim[i2] = (float)(2.0*(cr*qi + ci*qr));
        return;
    }
    int i3 = i2 - NCT;
    if (i3 < NEMB) {
        int k   = i3 % CH3;
        int pos = (i3 / CH3) % 16;
        int i   = k >> 1;
        float freq = expf(-logf(10000.0f) * (float)(2*i) / (float)CH3);
        float arg  = (float)pos * freq;
        g_emb[i3] = (k & 1) ? cosf(arg) : sinf(arg);
    }
}

// ---------------- build QtP / GTP (fragment-packed) per channel ----------------
__global__ __launch_bounds__(64) void build_kernel(const float* __restrict__ D) {
    __shared__ float smre[64][65];
    __shared__ float smim[64][65];
    __shared__ float kv[64];
    int c = blockIdx.x;
    int n = threadIdx.x;
    int nn = c*64 + n;
    float wr = g_wre[nn], wi = g_wim[nn];
    float cr = g_ctre[nn], ci = g_ctim[nn];
    float4* QtP = g_QtP + (size_t)c * 2048;
    float4* GTP = g_GTP + (size_t)c * 3072;

    // phase 1: powers w^0..w^63 per state n
    {
        float pr = 1.f, pi = 0.f;
        for (int d = 0; d < 64; ++d) {
            smre[d][n] = pr; smim[d][n] = pi;
            float t = pr*wr - pi*wi; pi = pr*wi + pi*wr; pr = t;
        }
    }
    __syncthreads();
    for (int p = n; p < 2048; p += 64) {
        int kb = p >> 8, mb = (p >> 5) & 7, ln = p & 31;
        int g = ln >> 2, tg = ln & 3;
        int m0 = mb*16 + g, k0 = kb*8 + tg;
        float4 v;
        #define QV(m,k) tf32rna(((m)&1) ? smim[63-(k)][(m)>>1] : smre[63-(k)][(m)>>1])
        v.x = QV(m0,   k0); v.y = QV(m0+8, k0);
        v.z = QV(m0, k0+4); v.w = QV(m0+8, k0+4);
        #undef QV
        QtP[p] = v;
    }
    __syncthreads();
    // phase 2: z = Ct*w^{t+1}: smre[t][n]=Re, smim[t][n]=-Im
    {
        float zr = cr*wr - ci*wi, zi = cr*wi + ci*wr;
        for (int t = 0; t < 64; ++t) {
            smre[t][n] = zr; smim[t][n] = -zi;
            float tt = zr*wr - zi*wi; zi = zr*wi + zi*wr; zr = tt;
        }
    }
    __syncthreads();
    for (int p = n; p < 2048; p += 64) {
        int kb = p >> 7, mb = (p >> 5) & 3, ln = p & 31;
        int g = ln >> 2, tg = ln & 3;
        int m0 = mb*16 + g, r0 = kb*8 + tg;
        float4 v;
        #define GV(t,r) tf32rna(((r)&1) ? smim[t][(r)>>1] : smre[t][(r)>>1])
        v.x = GV(m0,   r0); v.y = GV(m0+8, r0);
        v.z = GV(m0, r0+4); v.w = GV(m0+8, r0+4);
        #undef GV
        GTP[p] = v;
    }
    __syncthreads();
    // phase 3: K[d] = Re(sum_n Ct*w^d)
    {
        float zr = cr, zi = ci;
        for (int d = 0; d < 64; ++d) {
            smre[d][n] = zr;
            float tt = zr*wr - zi*wi; zi = zr*wi + zi*wr; zr = tt;
        }
    }
    __syncthreads();
    {
        float s = 0.f;
        for (int q = 0; q < 64; ++q) s += smre[n][q];
        kv[n] = s;
    }
    __syncthreads();
    float dc = D[c];
    for (int p = n; p < 1024; p += 64) {
        int kb = 16 + (p >> 7), mb = (p >> 5) & 3, ln = p & 31;
        int g = ln >> 2, tg = ln & 3;
        int m0 = mb*16 + g, r0 = kb*8 + tg;
        float4 v;
        #define TV(t,r) tf32rna((((t) >= (r)-128) ? kv[(t)-((r)-128)] : 0.f) + (((t) == (r)-128) ? dc : 0.f))
        v.x = TV(m0,   r0); v.y = TV(m0+8, r0);
        v.z = TV(m0, r0+4); v.w = TV(m0+8, r0+4);
        #undef TV
        GTP[2048 + p] = v;
    }
}

// ---------------- fused SSM (col-major smem): v=x+pe -> B=Qt@V -> scan -> Y=[G|T]@[S0;V] -> gelu ----------------
// one CTA per (b,c); 128 threads = 4 warps as 2(m) x 2(n)
// Vs[kcol][j]  (64 x 68)   V column-major: natural l-order, conflict-free
// Bs[kcol][n]  (64 x 132)  B / S0 column-major
#define SPV 68
#define SPB 132
#define SMEMSZ ((64*SPV + 64*SPB)*4)

__global__ __launch_bounds__(128) void fused_kernel(const float* __restrict__ xin) {
    extern __shared__ float sm[];
    float* Vs = sm;                  // [64][SPV]
    float* Bs = sm + 64*SPV;         // [64][SPB]

    int bc = blockIdx.x;
    int c  = bc & (Hc - 1);
    int t  = threadIdx.x;
    int lane = t & 31, wrp = t >> 5;
    int gID = lane >> 2, tig = lane & 3;
    int wm = wrp & 1, wn = wrp >> 1;   // 2(m) x 2(n)
    int cnb = wn << 5;                 // n-col base (0 / 32)

    const float4* QtP = g_QtP + (size_t)c * 2048;
    const float4* GTP = g_GTP + (size_t)c * 3072;

    // ---- v = x + posenc, natural order into Vs[kcol][j] (STS.128, conflict-free) ----
    {
        int cax; const float* et;
        if (c < CH3)        { cax = 0; et = g_emb + c; }
        else if (c < 2*CH3) { cax = 1; et = g_emb + 16*CH3 + (c - CH3); }
        else                { cax = 2; et = g_emb + 32*CH3 + (c - 2*CH3); }
        const float* xp = xin + (size_t)bc * Lt;
        #pragma unroll
        for (int p = 0; p < 8; ++p) {
            int l = (t + p*128) << 2;
            float4 xv = *(const float4*)&xp[l];
            float p0, p1, p2, p3;
            if (cax == 0)      { float e = et[(l >> 8)*CH3];        p0 = p1 = p2 = p3 = e; }
            else if (cax == 1) { float e = et[((l >> 4) & 15)*CH3]; p0 = p1 = p2 = p3 = e; }
            else {
                int lw = l & 15;
                p0 = et[lw*CH3]; p1 = et[(lw+1)*CH3]; p2 = et[(lw+2)*CH3]; p3 = et[(lw+3)*CH3];
            }
            int kcol = l >> 6, j = l & 63;
            *(float4*)&Vs[kcol*SPV + j] = make_float4(
                tf32rna(xv.x + p0), tf32rna(xv.y + p1),
                tf32rna(xv.z + p2), tf32rna(xv.w + p3));
        }
    }
    __syncthreads();

    // ---- pass A: B[n][kcol] = sum_j Qt[j][n] * V[j][kcol] ----
    #pragma unroll
    for (int mh = 0; mh < 2; ++mh) {
        float acc[2][4][4];
        #pragma unroll
        for (int mb = 0; mb < 2; ++mb)
            #pragma unroll
            for (int nt = 0; nt < 4; ++nt)
                #pragma unroll
                for (int r = 0; r < 4; ++r) acc[mb][nt][r] = 0.f;
        #pragma unroll
        for (int k8 = 0; k8 < 8; ++k8) {
            int kd = k8 << 3;
            float4 qf[2];
            #pragma unroll
            for (int mb = 0; mb < 2; ++mb)
                qf[mb] = QtP[(k8*8 + mh*4 + wm*2 + mb)*32 + lane];
            uint32_t b0[4], b1[4];
            #pragma unroll
            for (int nt = 0; nt < 4; ++nt) {
                int cn = cnb + (nt << 3) + gID;
                b0[nt] = __float_as_uint(Vs[cn*SPV + kd + tig    ]);
                b1[nt] = __float_as_uint(Vs[cn*SPV + kd + tig + 4]);
            }
            #pragma unroll
            for (int mb = 0; mb < 2; ++mb) {
                uint32_t a0 = __float_as_uint(qf[mb].x), a1 = __float_as_uint(qf[mb].y);
                uint32_t a2 = __float_as_uint(qf[mb].z), a3 = __float_as_uint(qf[mb].w);
                #pragma unroll
                for (int nt = 0; nt < 4; ++nt)
                    MMA_TF32(acc[mb][nt], a0, a1, a2, a3, b0[nt], b1[nt]);
            }
        }
        #pragma unroll
        for (int mb = 0; mb < 2; ++mb) {
            int row0 = mh*64 + wm*32 + mb*16 + gID;
            #pragma unroll
            for (int nt = 0; nt < 4; ++nt) {
                int col = cnb + (nt << 3) + (tig << 1);
                Bs[col*SPB + row0]           = acc[mb][nt][0];
                Bs[(col+1)*SPB + row0]       = acc[mb][nt][1];
                Bs[col*SPB + row0 + 8]       = acc[mb][nt][2];
                Bs[(col+1)*SPB + row0 + 8]   = acc[mb][nt][3];
            }
        }
    }
    __syncthreads();

    // ---- in-smem scan over 64 chunks: S0(k+1) = w^64*S0(k) + B(k); Bs := S0 (tf32) ----
    if (t < 64) {
        int nn = c*64 + t;
        float wr = g_wTre[nn], wi = g_wTim[nn];
        float sr = 0.f, si = 0.f;
        #pragma unroll 8
        for (int k = 0; k < 64; ++k) {
            float2* pp = (float2*)&Bs[k*SPB + 2*t];
            float2 bv = *pp;
            *pp = make_float2(tf32rna(sr), tf32rna(si));
            float nr = fmaf(wr, sr, fmaf(-wi, si, bv.x));
            si       = fmaf(wr, si, fmaf( wi, sr, bv.y));
            sr = nr;
        }
    }
    __syncthreads();

    // ---- pass C: Y[t][kcol] = sum_r GT[r][t] * X[r][kcol], X = [S0(128) ; V(64)] ----
    float accC[2][4][4];
    #pragma unroll
    for (int mb = 0; mb < 2; ++mb)
        #pragma unroll
        for (int nt = 0; nt < 4; ++nt)
            #pragma unroll
            for (int r = 0; r < 4; ++r) accC[mb][nt][r] = 0.f;

    #pragma unroll
    for (int s = 0; s < 3; ++s) {
        #pragma unroll
        for (int k8 = 0; k8 < 8; ++k8) {
            int kd = k8 << 3;
            float4 gf[2];
            #pragma unroll
            for (int mb = 0; mb < 2; ++mb)
                gf[mb] = GTP[((s*8 + k8)*4 + wm*2 + mb)*32 + lane];
            uint32_t b0[4], b1[4];
            #pragma unroll
            for (int nt = 0; nt < 4; ++nt) {
                int cn = cnb + (nt << 3) + gID;
                if (s < 2) {
                    b0[nt] = __float_as_uint(Bs[cn*SPB + s*64 + kd + tig    ]);
                    b1[nt] = __float_as_uint(Bs[cn*SPB + s*64 + kd + tig + 4]);
                } else {
                    b0[nt] = __float_as_uint(Vs[cn*SPV + kd + tig    ]);
                    b1[nt] = __float_as_uint(Vs[cn*SPV + kd + tig + 4]);
                }
            }
            #pragma unroll
            for (int mb = 0; mb < 2; ++mb) {
                uint32_t a0 = __float_as_uint(gf[mb].x), a1 = __float_as_uint(gf[mb].y);
                uint32_t a2 = __float_as_uint(gf[mb].z), a3 = __float_as_uint(gf[mb].w);
                #pragma unroll
                for (int nt = 0; nt < 4; ++nt)
                    MMA_TF32(accC[mb][nt], a0, a1, a2, a3, b0[nt], b1[nt]);
            }
        }
    }

    // ---- epilogue: l = kcol*64 + t, gelu, tf32 round ----
    float* yp = g_yT + (size_t)bc * Lt;
    #pragma unroll
    for (int mb = 0; mb < 2; ++mb) {
        int t0 = wm*32 + mb*16 + gID;
        #pragma unroll
        for (int nt = 0; nt < 4; ++nt) {
            int k0 = cnb + (nt << 3) + (tig << 1);
            yp[(size_t)k0    *64 + t0    ] = tf32rna(gelu_f(accC[mb][nt][0]));
            yp[(size_t)(k0+1)*64 + t0    ] = tf32rna(gelu_f(accC[mb][nt][1]));
            yp[(size_t)k0    *64 + t0 + 8] = tf32rna(gelu_f(accC[mb][nt][2]));
            yp[(size_t)(k0+1)*64 + t0 + 8] = tf32rna(gelu_f(accC[mb][nt][3]));
        }
    }
}

// ---------------- final tf32 GEMM: out = Wp(frag) @ yT + bias ----------------
// tile 128(o) x 128(l), BK=16, 256 threads = 8 warps as 4(o) x 2(l)
// A frags double-buffered (R12); B frags via paired float2 smem -> one LDS.64 each
__global__ __launch_bounds__(256, 2) void gemm_kernel(const float* __restrict__ bias,
                                                      float* __restrict__ out) {
    __shared__ float2 Ys2[2][8][132];   // [pair-row (k8i*4+tig)][col] = {y[k8+tig], y[k8+tig+4]}
    int b  = blockIdx.z;
    int oo = blockIdx.y << 7;
    int ll = blockIdx.x << 7;
    int t  = threadIdx.x;
    int lane = t & 31, wid = t >> 5;
    int om = (wid & 3) << 5;
    int on = (wid >> 2) << 6;
    int gID = lane >> 2, tig = lane & 3;

    // staging: thread handles pair-row pt (0..7) and 4 cols
    int pt  = t >> 5;                   // 0..7
    int lcp = (t & 31) << 2;            // 0..124
    int ra  = ((pt >> 2) << 3) + (pt & 3);   // rows 0..3, 8..11
    const float* Ypa = g_yT + ((size_t)b * Hc + ra) * Lt + ll + lcp;
    const float* Ypb = Ypa + 4*Lt;
    int MbBase = (oo >> 4) + ((wid & 3) << 1);

    float4 yva = *(const float4*)Ypa;
    float4 yvb = *(const float4*)Ypb;

    float4 af[2][2], afn[2][2];
    #pragma unroll
    for (int k8i = 0; k8i < 2; ++k8i)
        #pragma unroll
        for (int mt = 0; mt < 2; ++mt)
            af[k8i][mt] = g_Wp[(size_t)(k8i*32 + MbBase + mt)*32 + lane];

    float acc[2][8][4];
    #pragma unroll
    for (int mt = 0; mt < 2; ++mt)
        #pragma unroll
        for (int nt = 0; nt < 8; ++nt)
            #pragma unroll
            for (int r = 0; r < 4; ++r) acc[mt][nt][r] = 0.f;

    int buf = 0;
    for (int s = 0; s < Hc/16; ++s) {
        // interleave pairs: {ya[i], yb[i]} contiguous
        *(float4*)&Ys2[buf][pt][lcp]     = make_float4(yva.x, yvb.x, yva.y, yvb.y);
        *(float4*)&Ys2[buf][pt][lcp + 2] = make_float4(yva.z, yvb.z, yva.w, yvb.w);
        __syncthreads();
        if (s + 1 < Hc/16) {
            size_t ko = (size_t)(s + 1) * 16;
            yva = *(const float4*)(Ypa + ko * Lt);
            yvb = *(const float4*)(Ypb + ko * Lt);
            #pragma unroll
            for (int k8i = 0; k8i < 2; ++k8i)
                #pragma unroll
                for (int mt = 0; mt < 2; ++mt)
                    afn[k8i][mt] = g_Wp[(size_t)(((s+1)*2 + k8i)*32 + MbBase + mt)*32 + lane];
        }
        #pragma unroll
        for (int k8i = 0; k8i < 2; ++k8i) {
            uint32_t bf[8][2];
            #pragma unroll
            for (int nt = 0; nt < 8; ++nt) {
                int cn = on + (nt << 3) + gID;
                float2 bp = Ys2[buf][(k8i << 2) | tig][cn];
                bf[nt][0] = __float_as_uint(bp.x);
                bf[nt][1] = __float_as_uint(bp.y);
            }
            #pragma unroll
            for (int mt = 0; mt < 2; ++mt) {
                uint32_t a0 = __float_as_uint(af[k8i][mt].x), a1 = __float_as_uint(af[k8i][mt].y);
                uint32_t a2 = __float_as_uint(af[k8i][mt].z), a3 = __float_as_uint(af[k8i][mt].w);
                #pragma unroll
                for (int nt = 0; nt < 8; ++nt)
                    MMA_TF32(acc[mt][nt], a0, a1, a2, a3, bf[nt][0], bf[nt][1]);
            }
        }
        #pragma unroll
        for (int k8i = 0; k8i < 2; ++k8i)
            #pragma unroll
            for (int mt = 0; mt < 2; ++mt)
                af[k8i][mt] = afn[k8i][mt];
        buf ^= 1;
        __syncthreads();
    }

    #pragma unroll
    for (int mt = 0; mt < 2; ++mt) {
        int o0 = oo + om + (mt << 4) + gID;
        float b0 = __ldg(&bias[o0]);
        float b8 = __ldg(&bias[o0 + 8]);
        float* r0p = out + ((size_t)b * OUTc + o0)     * Lt + ll + on + (tig << 1);
        float* r8p = out + ((size_t)b * OUTc + o0 + 8) * Lt + ll + on + (tig << 1);
        #pragma unroll
        for (int nt = 0; nt < 8; ++nt) {
            *(float2*)(r0p + (nt << 3)) = make_float2(acc[mt][nt][0] + b0, acc[mt][nt][1] + b0);
            *(float2*)(r8p + (nt << 3)) = make_float2(acc[mt][nt][2] + b8, acc[mt][nt][3] + b8);
        }
    }
}

// ---------------- launch ----------------
extern "C" void kernel_launch(void* const* d_in, const int* in_sizes, int n_in,
                              void* d_out, int out_size) {
    const float* x      = (const float*)d_in[0];
    const float* log_dt = (const float*)d_in[1];
    const float* A_re   = (const float*)d_in[2];
    const float* A_im   = (const float*)d_in[3];
    const float* C_re   = (const float*)d_in[4];
    const float* C_im   = (const float*)d_in[5];
    const float* D      = (const float*)d_in[6];
    const float* W      = (const float*)d_in[7];
    const float* bias   = (const float*)d_in[8];
    float* out = (float*)d_out;

    cudaFuncSetAttribute(fused_kernel, cudaFuncAttributeMaxDynamicSharedMemorySize, SMEMSZ);

    int nprep = NWP + NCT + NEMB;
    prep_all_kernel<<<(nprep + 255)/256, 256>>>(W, log_dt, A_re, A_im, C_re, C_im);
    build_kernel<<<Hc, 64>>>(D);
    fused_kernel<<<BC, 128, SMEMSZ>>>(x);
    gemm_kernel<<<dim3(Lt/128, OUTc/128, BSz), 256>>>(bias, out);
}

// round 17
// speedup vs baseline: 1.3428x; 1.0148x over previous
#include <cuda_runtime.h>
#include <math.h>
#include <stdint.h>

#define Hc   1024
#define Nst  64
#define Lt   4096
#define OUTc 512
#define BSz  2
#define BC   (BSz*Hc)
#define CH3  342   // per-axis posenc channels

// ---------------- helpers ----------------
__device__ __forceinline__ float tf32rna(float v) {
    uint32_t u; asm("cvt.rna.tf32.f32 %0, %1;" : "=r"(u) : "f"(v));
    return __uint_as_float(u);
}
__device__ __forceinline__ float gelu_f(float s) {
    float a2 = 1.5957691216057308f * fmaf(0.044715f * s, s * s, s);
    float e  = __expf(a2);
    float th = 1.0f - __fdividef(2.0f, e + 1.0f);
    return 0.5f * s * (1.0f + th);
}
#define MMA_TF32(acc, a0,a1,a2,a3, b0,b1) \
    asm("mma.sync.aligned.m16n8k8.row.col.f32.tf32.tf32.f32 " \
        "{%0,%1,%2,%3},{%4,%5,%6,%7},{%8,%9},{%0,%1,%2,%3};" \
        : "+f"(acc[0]), "+f"(acc[1]), "+f"(acc[2]), "+f"(acc[3]) \
        : "r"(a0), "r"(a1), "r"(a2), "r"(a3), "r"(b0), "r"(b1))

// ---------------- scratch ----------------
__device__ float  g_yT[BC*Lt];          // gelu output, (b, c, l), tf32
__device__ float4 g_Wp [128*32*32];     // W fragment-packed: [kb][mb][lane]
__device__ float4 g_QtP[Hc*2048];       // per c: [kb0..7][mb0..7][lane]
__device__ float4 g_GTP[Hc*3072];       // per c: [kb0..23][mb0..3][lane]
__device__ float g_wre[Hc*Nst],  g_wim[Hc*Nst];
__device__ float g_wTre[Hc*Nst], g_wTim[Hc*Nst];   // w^64
__device__ float g_ctre[Hc*Nst], g_ctim[Hc*Nst];
__device__ float g_emb[3*16*CH3];

// ---------------- merged prep: W fragment-pack | discretize | emb ----------------
#define NWP (128*32*32)
#define NCT (Hc*Nst)
#define NEMB (3*16*CH3)

__global__ void prep_all_kernel(const float* __restrict__ W,
                                const float* __restrict__ log_dt,
                                const float* __restrict__ Are, const float* __restrict__ Aim,
                                const float* __restrict__ Cre, const float* __restrict__ Cim) {
    int idx = blockIdx.x * blockDim.x + threadIdx.x;
    if (idx < NWP) {
        int kb = idx >> 10;
        int mb = (idx >> 5) & 31;
        int ln = idx & 31;
        int g = ln >> 2, tg = ln & 3;
        int m0 = mb*16 + g, k0 = kb*8 + tg;
        float4 v;
        v.x = tf32rna(W[(size_t)k0*OUTc + m0]);
        v.y = tf32rna(W[(size_t)k0*OUTc + m0 + 8]);
        v.z = tf32rna(W[(size_t)(k0+4)*OUTc + m0]);
        v.w = tf32rna(W[(size_t)(k0+4)*OUTc + m0 + 8]);
        g_Wp[idx] = v;
        return;
    }
    int i2 = idx - NWP;
    if (i2 < NCT) {
        int c = i2 >> 6;
        double dt  = exp((double)log_dt[c]);
        double ar  = (double)Are[i2], ai = (double)Aim[i2];
        double dar = dt*ar, dai = dt*ai;
        double er  = exp(dar);
        double wr = er*cos(dai), wi = er*sin(dai);
        g_wre[i2] = (float)wr; g_wim[i2] = (float)wi;
        double erT = exp(64.0 * dar);
        g_wTre[i2] = (float)(erT*cos(64.0*dai));
        g_wTim[i2] = (float)(erT*sin(64.0*dai));
        double nr = wr - 1.0, ni = wi;
        double inv = 1.0 / (ar*ar + ai*ai);
        double qr = (nr*ar + ni*ai) * inv;
        double qi = (ni*ar - nr*ai) * inv;
        double cr = (double)Cre[i2], ci = (double)Cim[i2];
        g_ctre[i2] = (float)(2.0*(cr*qr - ci*qi));
        g_ctim[i2] = (float)(2.0*(cr*qi + ci*qr));
        return;
    }
    int i3 = i2 - NCT;
    if (i3 < NEMB) {
        int k   = i3 % CH3;
        int pos = (i3 / CH3) % 16;
        int i   = k >> 1;
        float freq = expf(-logf(10000.0f) * (float)(2*i) / (float)CH3);
        float arg  = (float)pos * freq;
        g_emb[i3] = (k & 1) ? cosf(arg) : sinf(arg);
    }
}

// ---------------- build QtP / GTP (fragment-packed) per channel, 256 threads ----------------
__global__ __launch_bounds__(256) void build_kernel(const float* __restrict__ D) {
    __shared__ float smre[64][65];
    __shared__ float smim[64][65];
    __shared__ float kv[64];
    int c = blockIdx.x;
    int t = threadIdx.x;
    int n = t & 63;
    int quad = t >> 6;
    int nn = c*64 + n;
    float wr = g_wre[nn], wi = g_wim[nn];
    float cr = g_ctre[nn], ci = g_ctim[nn];
    float4* QtP = g_QtP + (size_t)c * 2048;
    float4* GTP = g_GTP + (size_t)c * 3072;

    // phase 1: powers w^0..w^63 per state n (quadrant 0 only)
    if (quad == 0) {
        float pr = 1.f, pi = 0.f;
        for (int d = 0; d < 64; ++d) {
            smre[d][n] = pr; smim[d][n] = pi;
            float tt = pr*wr - pi*wi; pi = pr*wi + pi*wr; pr = tt;
        }
    }
    __syncthreads();
    for (int p = t; p < 2048; p += 256) {
        int kb = p >> 8, mb = (p >> 5) & 7, ln = p & 31;
        int g = ln >> 2, tg = ln & 3;
        int m0 = mb*16 + g, k0 = kb*8 + tg;
        float4 v;
        #define QV(m,k) tf32rna(((m)&1) ? smim[63-(k)][(m)>>1] : smre[63-(k)][(m)>>1])
        v.x = QV(m0,   k0); v.y = QV(m0+8, k0);
        v.z = QV(m0, k0+4); v.w = QV(m0+8, k0+4);
        #undef QV
        QtP[p] = v;
    }
    __syncthreads();
    // phase 2: z = Ct*w^{t+1}: smre[t][n]=Re, smim[t][n]=-Im
    if (quad == 0) {
        float zr = cr*wr - ci*wi, zi = cr*wi + ci*wr;
        for (int tt_ = 0; tt_ < 64; ++tt_) {
            smre[tt_][n] = zr; smim[tt_][n] = -zi;
            float tt = zr*wr - zi*wi; zi = zr*wi + zi*wr; zr = tt;
        }
    }
    __syncthreads();
    for (int p = t; p < 2048; p += 256) {
        int kb = p >> 7, mb = (p >> 5) & 3, ln = p & 31;
        int g = ln >> 2, tg = ln & 3;
        int m0 = mb*16 + g, r0 = kb*8 + tg;
        float4 v;
        #define GV(t_,r) tf32rna(((r)&1) ? smim[t_][(r)>>1] : smre[t_][(r)>>1])
        v.x = GV(m0,   r0); v.y = GV(m0+8, r0);
        v.z = GV(m0, r0+4); v.w = GV(m0+8, r0+4);
        #undef GV
        GTP[p] = v;
    }
    __syncthreads();
    // phase 3: K[d] = Re(sum_n Ct*w^d)
    if (quad == 0) {
        float zr = cr, zi = ci;
        for (int d = 0; d < 64; ++d) {
            smre[d][n] = zr;
            float tt = zr*wr - zi*wi; zi = zr*wi + zi*wr; zr = tt;
        }
    }
    __syncthreads();
    if (quad == 0) {
        float s = 0.f;
        for (int q = 0; q < 64; ++q) s += smre[n][q];
        kv[n] = s;
    }
    __syncthreads();
    float dc = D[c];
    for (int p = t; p < 1024; p += 256) {
        int kb = 16 + (p >> 7), mb = (p >> 5) & 3, ln = p & 31;
        int g = ln >> 2, tg = ln & 3;
        int m0 = mb*16 + g, r0 = kb*8 + tg;
        float4 v;
        #define TV(t_,r) tf32rna((((t_) >= (r)-128) ? kv[(t_)-((r)-128)] : 0.f) + (((t_) == (r)-128) ? dc : 0.f))
        v.x = TV(m0,   r0); v.y = TV(m0+8, r0);
        v.z = TV(m0, r0+4); v.w = TV(m0+8, r0+4);
        #undef TV
        GTP[2048 + p] = v;
    }
}

// ---------------- fused SSM (col-major smem, 256 threads = 8 warps as 2m x 4n) ----------------
// Vs[kcol][j]  (64 x 68)   V column-major
// Bs[kcol][n]  (64 x 132)  B / S0 column-major
#define SPV 68
#define SPB 132
#define SMEMSZ ((64*SPV + 64*SPB)*4)

__global__ __launch_bounds__(256) void fused_kernel(const float* __restrict__ xin) {
    extern __shared__ float sm[];
    float* Vs = sm;                  // [64][SPV]
    float* Bs = sm + 64*SPV;         // [64][SPB]

    int bc = blockIdx.x;
    int c  = bc & (Hc - 1);
    int t  = threadIdx.x;
    int lane = t & 31, wrp = t >> 5;
    int gID = lane >> 2, tig = lane & 3;
    int wm = wrp & 1, wn = wrp >> 1;   // 2(m) x 4(n)
    int cnb = wn << 4;                 // n-col base: 0,16,32,48

    const float4* QtP = g_QtP + (size_t)c * 2048;
    const float4* GTP = g_GTP + (size_t)c * 3072;

    // ---- v = x + posenc, natural order into Vs[kcol][j] ----
    {
        int cax; const float* et;
        if (c < CH3)        { cax = 0; et = g_emb + c; }
        else if (c < 2*CH3) { cax = 1; et = g_emb + 16*CH3 + (c - CH3); }
        else                { cax = 2; et = g_emb + 32*CH3 + (c - 2*CH3); }
        const float* xp = xin + (size_t)bc * Lt;
        #pragma unroll
        for (int p = 0; p < 4; ++p) {
            int l = (t + p*256) << 2;
            float4 xv = *(const float4*)&xp[l];
            float p0, p1, p2, p3;
            if (cax == 0)      { float e = et[(l >> 8)*CH3];        p0 = p1 = p2 = p3 = e; }
            else if (cax == 1) { float e = et[((l >> 4) & 15)*CH3]; p0 = p1 = p2 = p3 = e; }
            else {
                int lw = l & 15;
                p0 = et[lw*CH3]; p1 = et[(lw+1)*CH3]; p2 = et[(lw+2)*CH3]; p3 = et[(lw+3)*CH3];
            }
            int kcol = l >> 6, j = l & 63;
            *(float4*)&Vs[kcol*SPV + j] = make_float4(
                tf32rna(xv.x + p0), tf32rna(xv.y + p1),
                tf32rna(xv.z + p2), tf32rna(xv.w + p3));
        }
    }
    __syncthreads();

    // ---- pass A: B[n][kcol] = sum_j Qt[j][n] * V[j][kcol] ----
    #pragma unroll
    for (int mh = 0; mh < 2; ++mh) {
        float acc[2][2][4];
        #pragma unroll
        for (int mb = 0; mb < 2; ++mb)
            #pragma unroll
            for (int nt = 0; nt < 2; ++nt)
                #pragma unroll
                for (int r = 0; r < 4; ++r) acc[mb][nt][r] = 0.f;
        #pragma unroll
        for (int k8 = 0; k8 < 8; ++k8) {
            int kd = k8 << 3;
            float4 qf[2];
            #pragma unroll
            for (int mb = 0; mb < 2; ++mb)
                qf[mb] = QtP[(k8*8 + mh*4 + wm*2 + mb)*32 + lane];
            uint32_t b0[2], b1[2];
            #pragma unroll
            for (int nt = 0; nt < 2; ++nt) {
                int cn = cnb + (nt << 3) + gID;
                b0[nt] = __float_as_uint(Vs[cn*SPV + kd + tig    ]);
                b1[nt] = __float_as_uint(Vs[cn*SPV + kd + tig + 4]);
            }
            #pragma unroll
            for (int mb = 0; mb < 2; ++mb) {
                uint32_t a0 = __float_as_uint(qf[mb].x), a1 = __float_as_uint(qf[mb].y);
                uint32_t a2 = __float_as_uint(qf[mb].z), a3 = __float_as_uint(qf[mb].w);
                #pragma unroll
                for (int nt = 0; nt < 2; ++nt)
                    MMA_TF32(acc[mb][nt], a0, a1, a2, a3, b0[nt], b1[nt]);
            }
        }
        #pragma unroll
        for (int mb = 0; mb < 2; ++mb) {
            int row0 = mh*64 + wm*32 + mb*16 + gID;
            #pragma unroll
            for (int nt = 0; nt < 2; ++nt) {
                int col = cnb + (nt << 3) + (tig << 1);
                Bs[col*SPB + row0]           = acc[mb][nt][0];
                Bs[(col+1)*SPB + row0]       = acc[mb][nt][1];
                Bs[col*SPB + row0 + 8]       = acc[mb][nt][2];
                Bs[(col+1)*SPB + row0 + 8]   = acc[mb][nt][3];
            }
        }
    }
    __syncthreads();

    // ---- in-smem scan over 64 chunks: S0(k+1) = w^64*S0(k) + B(k); Bs := S0 (tf32) ----
    if (t < 64) {
        int nn = c*64 + t;
        float wr = g_wTre[nn], wi = g_wTim[nn];
        float sr = 0.f, si = 0.f;
        #pragma unroll 8
        for (int k = 0; k < 64; ++k) {
            float2* pp = (float2*)&Bs[k*SPB + 2*t];
            float2 bv = *pp;
            *pp = make_float2(tf32rna(sr), tf32rna(si));
            float nr = fmaf(wr, sr, fmaf(-wi, si, bv.x));
            si       = fmaf(wr, si, fmaf( wi, sr, bv.y));
            sr = nr;
        }
    }
    __syncthreads();

    // ---- pass C: Y[t][kcol] = sum_r GT[r][t] * X[r][kcol], X = [S0(128) ; V(64)] ----
    float accC[2][2][4];
    #pragma unroll
    for (int mb = 0; mb < 2; ++mb)
        #pragma unroll
        for (int nt = 0; nt < 2; ++nt)
            #pragma unroll
            for (int r = 0; r < 4; ++r) accC[mb][nt][r] = 0.f;

    #pragma unroll
    for (int s = 0; s < 3; ++s) {
        #pragma unroll
        for (int k8 = 0; k8 < 8; ++k8) {
            int kd = k8 << 3;
            float4 gf[2];
            #pragma unroll
            for (int mb = 0; mb < 2; ++mb)
                gf[mb] = GTP[((s*8 + k8)*4 + wm*2 + mb)*32 + lane];
            uint32_t b0[2], b1[2];
            #pragma unroll
            for (int nt = 0; nt < 2; ++nt) {
                int cn = cnb + (nt << 3) + gID;
                if (s < 2) {
                    b0[nt] = __float_as_uint(Bs[cn*SPB + s*64 + kd + tig    ]);
                    b1[nt] = __float_as_uint(Bs[cn*SPB + s*64 + kd + tig + 4]);
                } else {
                    b0[nt] = __float_as_uint(Vs[cn*SPV + kd + tig    ]);
                    b1[nt] = __float_as_uint(Vs[cn*SPV + kd + tig + 4]);
                }
            }
            #pragma unroll
            for (int mb = 0; mb < 2; ++mb) {
                uint32_t a0 = __float_as_uint(gf[mb].x), a1 = __float_as_uint(gf[mb].y);
                uint32_t a2 = __float_as_uint(gf[mb].z), a3 = __float_as_uint(gf[mb].w);
                #pragma unroll
                for (int nt = 0; nt < 2; ++nt)
                    MMA_TF32(accC[mb][nt], a0, a1, a2, a3, b0[nt], b1[nt]);
            }
        }
    }

    // ---- epilogue: l = kcol*64 + t, gelu, tf32 round ----
    float* yp = g_yT + (size_t)bc * Lt;
    #pragma unroll
    for (int mb = 0; mb < 2; ++mb) {
        int t0 = wm*32 + mb*16 + gID;
        #pragma unroll
        for (int nt = 0; nt < 2; ++nt) {
            int k0 = cnb + (nt << 3) + (tig << 1);
            yp[(size_t)k0    *64 + t0    ] = tf32rna(gelu_f(accC[mb][nt][0]));
            yp[(size_t)(k0+1)*64 + t0    ] = tf32rna(gelu_f(accC[mb][nt][1]));
            yp[(size_t)k0    *64 + t0 + 8] = tf32rna(gelu_f(accC[mb][nt][2]));
            yp[(size_t)(k0+1)*64 + t0 + 8] = tf32rna(gelu_f(accC[mb][nt][3]));
        }
    }
}

// ---------------- final tf32 GEMM: out = Wp(frag) @ yT + bias ----------------
// tile 128(o) x 128(l), BK=16, 256 threads = 8 warps as 4(o) x 2(l)
// A frags double-buffered; B frags via paired float2 smem; ONE sync per iter
__global__ __launch_bounds__(256, 2) void gemm_kernel(const float* __restrict__ bias,
                                                      float* __restrict__ out) {
    __shared__ float2 Ys2[2][8][132];   // [pair-row (k8i*4+tig)][col] = {y[k8+tig], y[k8+tig+4]}
    int b  = blockIdx.z;
    int oo = blockIdx.y << 7;
    int ll = blockIdx.x << 7;
    int t  = threadIdx.x;
    int lane = t & 31, wid = t >> 5;
    int om = (wid & 3) << 5;
    int on = (wid >> 2) << 6;
    int gID = lane >> 2, tig = lane & 3;

    int pt  = t >> 5;                   // 0..7
    int lcp = (t & 31) << 2;            // 0..124
    int ra  = ((pt >> 2) << 3) + (pt & 3);   // rows 0..3, 8..11
    const float* Ypa = g_yT + ((size_t)b * Hc + ra) * Lt + ll + lcp;
    const float* Ypb = Ypa + 4*Lt;
    int MbBase = (oo >> 4) + ((wid & 3) << 1);

    float4 yva = *(const float4*)Ypa;
    float4 yvb = *(const float4*)Ypb;

    float4 af[2][2], afn[2][2];
    #pragma unroll
    for (int k8i = 0; k8i < 2; ++k8i)
        #pragma unroll
        for (int mt = 0; mt < 2; ++mt)
            af[k8i][mt] = g_Wp[(size_t)(k8i*32 + MbBase + mt)*32 + lane];

    float acc[2][8][4];
    #pragma unroll
    for (int mt = 0; mt < 2; ++mt)
        #pragma unroll
        for (int nt = 0; nt < 8; ++nt)
            #pragma unroll
            for (int r = 0; r < 4; ++r) acc[mt][nt][r] = 0.f;

    int buf = 0;
    for (int s = 0; s < Hc/16; ++s) {
        *(float4*)&Ys2[buf][pt][lcp]     = make_float4(yva.x, yvb.x, yva.y, yvb.y);
        *(float4*)&Ys2[buf][pt][lcp + 2] = make_float4(yva.z, yvb.z, yva.w, yvb.w);
        __syncthreads();
        if (s + 1 < Hc/16) {
            size_t ko = (size_t)(s + 1) * 16;
            yva = *(const float4*)(Ypa + ko * Lt);
            yvb = *(const float4*)(Ypb + ko * Lt);
            #pragma unroll
            for (int k8i = 0; k8i < 2; ++k8i)
                #pragma unroll
                for (int mt = 0; mt < 2; ++mt)
                    afn[k8i][mt] = g_Wp[(size_t)(((s+1)*2 + k8i)*32 + MbBase + mt)*32 + lane];
        }
        #pragma unroll
        for (int k8i = 0; k8i < 2; ++k8i) {
            uint32_t bf[8][2];
            #pragma unroll
            for (int nt = 0; nt < 8; ++nt) {
                int cn = on + (nt << 3) + gID;
                float2 bp = Ys2[buf][(k8i << 2) | tig][cn];
                bf[nt][0] = __float_as_uint(bp.x);
                bf[nt][1] = __float_as_uint(bp.y);
            }
            #pragma unroll
            for (int mt = 0; mt < 2; ++mt) {
                uint32_t a0 = __float_as_uint(af[k8i][mt].x), a1 = __float_as_uint(af[k8i][mt].y);
                uint32_t a2 = __float_as_uint(af[k8i][mt].z), a3 = __float_as_uint(af[k8i][mt].w);
                #pragma unroll
                for (int nt = 0; nt < 8; ++nt)
                    MMA_TF32(acc[mt][nt], a0, a1, a2, a3, bf[nt][0], bf[nt][1]);
            }
        }
        #pragma unroll
        for (int k8i = 0; k8i < 2; ++k8i)
            #pragma unroll
            for (int mt = 0; mt < 2; ++mt)
                af[k8i][mt] = afn[k8i][mt];
        buf ^= 1;   // next store targets the other buffer: no second sync needed
    }

    #pragma unroll
    for (int mt = 0; mt < 2; ++mt) {
        int o0 = oo + om + (mt << 4) + gID;
        float b0 = __ldg(&bias[o0]);
        float b8 = __ldg(&bias[o0 + 8]);
        float* r0p = out + ((size_t)b * OUTc + o0)     * Lt + ll + on + (tig << 1);
        float* r8p = out + ((size_t)b * OUTc + o0 + 8) * Lt + ll + on + (tig << 1);
        #pragma unroll
        for (int nt = 0; nt < 8; ++nt) {
            *(float2*)(r0p + (nt << 3)) = make_float2(acc[mt][nt][0] + b0, acc[mt][nt][1] + b0);
            *(float2*)(r8p + (nt << 3)) = make_float2(acc[mt][nt][2] + b8, acc[mt][nt][3] + b8);
        }
    }
}

// ---------------- launch ----------------
extern "C" void kernel_launch(void* const* d_in, const int* in_sizes, int n_in,
                              void* d_out, int out_size) {
    const float* x      = (const float*)d_in[0];
    const float* log_dt = (const float*)d_in[1];
    const float* A_re   = (const float*)d_in[2];
    const float* A_im   = (const float*)d_in[3];
    const float* C_re   = (const float*)d_in[4];
    const float* C_im   = (const float*)d_in[5];
    const float* D      = (const float*)d_in[6];
    const float* W      = (const float*)d_in[7];
    const float* bias   = (const float*)d_in[8];
    float* out = (float*)d_out;

    cudaFuncSetAttribute(fused_kernel, cudaFuncAttributeMaxDynamicSharedMemorySize, SMEMSZ);

    int nprep = NWP + NCT + NEMB;
    prep_all_kernel<<<(nprep + 255)/256, 256>>>(W, log_dt, A_re, A_im, C_re, C_im);
    build_kernel<<<Hc, 256>>>(D);
    fused_kernel<<<BC, 256, SMEMSZ>>>(x);
    gemm_kernel<<<dim3(Lt/128, OUTc/128, BSz), 256>>>(bias, out);
}